// round 2
// baseline (speedup 1.0000x reference)
#include <cuda_runtime.h>
#include <cuda_bf16.h>
#include <math.h>

// Problem constants
#define Bsz 2
#define Cch 512
#define Gg  8
#define Cg  64
#define Hh  32
#define Ww  32
#define Pp  1024          // H*W
#define H2  8
#define W2  8
#define P2  64            // H2*W2
#define NHEADS 8
#define DH  64
#define SCALE 0.125f

// ---------------- scratch (static device globals; no allocation) ----------------
__device__ float g_xn  [Bsz*Cch*Pp];     // batchnorm1 output
__device__ float g_q   [Bsz*Cch*Pp];     // q (unscaled)
__device__ float g_off1[16*Cg*P2];       // depthwise conv + gelu
__device__ float g_grid[16*P2*2];        // vgrid_scaled (vx,vy) per (bg,j)
__device__ float g_kv  [16*Cg*P2];       // sampled kv
__device__ float g_k   [Bsz*Cch*P2];
__device__ float g_v   [Bsz*Cch*P2];
__device__ float g_bias[16*Pp*P2];       // cpb bias [bg][i][j]
__device__ float g_ao  [Bsz*Cch*Pp];     // attention output (pre out-proj)
__device__ float g_x1  [Bsz*Cch*Pp];     // x + attn branch
__device__ float g_h   [Bsz*Cch*Pp];     // batchnorm2 output
__device__ float g_m1  [Bsz*2048*Pp];    // mlp hidden

// ---------------- batchnorm (mean/var over B,H,W per channel) ----------------
__global__ void bn_kernel(const float* __restrict__ x, const float* __restrict__ g,
                          const float* __restrict__ b, float* __restrict__ y) {
    int c = blockIdx.x, t = threadIdx.x;
    __shared__ float ssum[256], ssq[256];
    float s = 0.f, q = 0.f;
    for (int idx = t; idx < 2048; idx += 256) {
        int bb = idx >> 10, p = idx & 1023;
        float v = x[bb*(Cch*Pp) + c*Pp + p];
        s += v; q += v*v;
    }
    ssum[t] = s; ssq[t] = q; __syncthreads();
    for (int o = 128; o > 0; o >>= 1) {
        if (t < o) { ssum[t] += ssum[t+o]; ssq[t] += ssq[t+o]; }
        __syncthreads();
    }
    float m  = ssum[0] * (1.f/2048.f);
    float var = ssq[0] * (1.f/2048.f) - m*m;
    float rs = rsqrtf(var + 1e-5f);
    float gg = g[c] * rs;
    float bb2 = b[c] - m * gg;
    for (int idx = t; idx < 2048; idx += 256) {
        int bb = idx >> 10, p = idx & 1023;
        y[bb*(Cch*Pp) + c*Pp + p] = x[bb*(Cch*Pp) + c*Pp + p] * gg + bb2;
    }
}

// ---------------- grouped 1x1 conv: per (b,g): out[o][p] = sum_c in[c][p]*w[g][o][c] ----------------
__global__ void gconv_kernel(const float* __restrict__ in, const float* __restrict__ w,
                             float* __restrict__ out, int P) {
    int bg = blockIdx.x, pt = blockIdx.y;
    int grp = bg & 7;
    const float* A  = in + (size_t)bg*Cg*P + pt*64;
    const float* Wg = w + grp*4096;
    float* O        = out + (size_t)bg*Cg*P + pt*64;
    __shared__ float As[64][64];
    __shared__ float Ws[64][64];   // [o][c]
    int t = threadIdx.x;
    for (int idx = t; idx < 4096; idx += 256) {
        int r = idx >> 6, q = idx & 63;
        As[r][q] = A[r*P + q];
        ((float*)Ws)[idx] = Wg[idx];
    }
    __syncthreads();
    int tp = (t & 15) * 4, to = (t >> 4) * 4;
    float acc[4][4] = {};
    #pragma unroll
    for (int c = 0; c < 64; c += 4) {
        float4 a[4], wv[4];
        #pragma unroll
        for (int u = 0; u < 4; u++) a[u] = *(const float4*)&As[c+u][tp];
        #pragma unroll
        for (int oi = 0; oi < 4; oi++) wv[oi] = *(const float4*)&Ws[to+oi][c];
        #pragma unroll
        for (int oi = 0; oi < 4; oi++) {
            float wf[4] = {wv[oi].x, wv[oi].y, wv[oi].z, wv[oi].w};
            #pragma unroll
            for (int u = 0; u < 4; u++) {
                acc[oi][0] += wf[u]*a[u].x; acc[oi][1] += wf[u]*a[u].y;
                acc[oi][2] += wf[u]*a[u].z; acc[oi][3] += wf[u]*a[u].w;
            }
        }
    }
    #pragma unroll
    for (int oi = 0; oi < 4; oi++)
        #pragma unroll
        for (int pj = 0; pj < 4; pj++)
            O[(to+oi)*P + tp+pj] = acc[oi][pj];
}

// ---------------- depthwise 6x6 stride-4 pad-1 conv + bias + exact gelu ----------------
__global__ void dwconv_kernel(const float* __restrict__ q, const float* __restrict__ dw,
                              const float* __restrict__ db, float* __restrict__ out) {
    int idx = blockIdx.x*blockDim.x + threadIdx.x;
    if (idx >= 16*Cg*P2) return;
    int p = idx & 63, c = (idx >> 6) & 63, bg = idx >> 12;
    int oy = p >> 3, ox = p & 7;
    float acc = db[c];
    const float* ip = q + (size_t)bg*Cg*Pp + c*Pp;
    const float* wp = dw + c*36;
    #pragma unroll
    for (int ky = 0; ky < 6; ky++) {
        int iy = oy*4 - 1 + ky;
        if (iy < 0 || iy >= 32) continue;
        #pragma unroll
        for (int kx = 0; kx < 6; kx++) {
            int ix = ox*4 - 1 + kx;
            if (ix < 0 || ix >= 32) continue;
            acc += ip[iy*32 + ix] * wp[ky*6 + kx];
        }
    }
    out[idx] = 0.5f * acc * (1.f + erff(acc * 0.70710678118654752f));
}

// ---------------- pointwise 64->2, tanh*4, build normalized sample grid ----------------
__global__ void offset_kernel(const float* __restrict__ off1, const float* __restrict__ pw,
                              float* __restrict__ grid) {
    int bg = blockIdx.x, p = threadIdx.x;  // 64 threads
    float s0 = 0.f, s1 = 0.f;
    const float* base = off1 + bg*(Cg*P2);
    for (int c = 0; c < 64; c++) {
        float v = base[c*64 + p];
        s0 += v * pw[c];
        s1 += v * pw[64 + c];
    }
    float ox = tanhf(s0) * 4.f, oy = tanhf(s1) * 4.f;
    float gx = (float)(p & 7), gy = (float)(p >> 3);
    float vx = 2.f * (gx + ox) * (1.f/7.f) - 1.f;
    float vy = 2.f * (gy + oy) * (1.f/7.f) - 1.f;
    grid[bg*128 + p*2]     = vx;
    grid[bg*128 + p*2 + 1] = vy;
}

// ---------------- bilinear grid sample (zero pad) ----------------
__global__ void gsample_kernel(const float* __restrict__ xn, const float* __restrict__ grid,
                               float* __restrict__ kv) {
    int idx = blockIdx.x*blockDim.x + threadIdx.x;
    if (idx >= 16*Cg*P2) return;
    int p = idx & 63, c = (idx >> 6) & 63, bg = idx >> 12;
    float vx = grid[bg*128 + p*2], vy = grid[bg*128 + p*2 + 1];
    float x = ((vx + 1.f) * 32.f - 1.f) * 0.5f;
    float y = ((vy + 1.f) * 32.f - 1.f) * 0.5f;
    float x0f = floorf(x), y0f = floorf(y);
    int x0 = (int)x0f, y0 = (int)y0f;
    float wx = x - x0f, wy = y - y0f;
    const float* im = xn + (size_t)bg*Cg*Pp + c*Pp;
    float v00 = (x0   >= 0 && x0   < 32 && y0   >= 0 && y0   < 32) ? im[y0*32 + x0]       : 0.f;
    float v10 = (x0+1 >= 0 && x0+1 < 32 && y0   >= 0 && y0   < 32) ? im[y0*32 + x0+1]     : 0.f;
    float v01 = (x0   >= 0 && x0   < 32 && y0+1 >= 0 && y0+1 < 32) ? im[(y0+1)*32 + x0]   : 0.f;
    float v11 = (x0+1 >= 0 && x0+1 < 32 && y0+1 >= 0 && y0+1 < 32) ? im[(y0+1)*32 + x0+1] : 0.f;
    kv[idx] = v00*(1.f-wx)*(1.f-wy) + v10*wx*(1.f-wy) + v01*(1.f-wx)*wy + v11*wx*wy;
}

// ---------------- CPB bias MLP: bias[bg][i][j] ----------------
// block: (bgj pair, 64 i's). 128 threads. smem: W1 64KB + h1 + f features.
__global__ void bias_kernel(const float* __restrict__ grid,
                            const float* __restrict__ w0, const float* __restrict__ b0,
                            const float* __restrict__ w1, const float* __restrict__ b1,
                            const float* __restrict__ w2, const float* __restrict__ b2,
                            float* __restrict__ bias) {
    extern __shared__ float sm[];
    float* W1s = sm;                   // 16384
    float* h1  = sm + 16384;           // 128*32 = 4096
    float* sfx = h1 + 4096;            // 64
    float* sfy = sfx + 64;             // 64
    float* sw0 = sfy + 64;             // 256
    float* sb0 = sw0 + 256;            // 128

    int t = threadIdx.x;                       // 128
    int bgj = blockIdx.x;
    int bg = bgj >> 6, j = bgj & 63;
    int ibase0 = blockIdx.y * 64;

    for (int idx = t; idx < 16384; idx += 128) W1s[idx] = w1[idx];
    for (int idx = t; idx < 256;   idx += 128) sw0[idx] = w0[idx];
    if (t < 128) sb0[t] = b0[t];

    float kvx = grid[bg*128 + j*2], kvy = grid[bg*128 + j*2 + 1];
    if (t < 64) {
        int i = ibase0 + t;
        float qx = 2.f * (float)(i & 31) * (1.f/31.f) - 1.f;
        float qy = 2.f * (float)(i >> 5) * (1.f/31.f) - 1.f;
        float px = qx - kvx, py = qy - kvy;
        sfx[t] = copysignf(log1pf(fabsf(px)), px);
        sfy[t] = copysignf(log1pf(fabsf(py)), py);
    }
    __syncthreads();

    int lane = t & 31, warp = t >> 5;
    int c4 = lane * 4;
    float b1r[4], w2r[4];
    #pragma unroll
    for (int k = 0; k < 4; k++) { b1r[k] = b1[c4+k]; w2r[k] = w2[c4+k]; }
    float b2v = b2[0];

    for (int batch = 0; batch < 2; batch++) {
        int ib0 = batch * 32;
        // h1[s][il] layout: flat = s*32 + il (32 i's)
        for (int f = t; f < 4096; f += 128) {
            int s = f >> 5, il = f & 31;
            float v = sfx[ib0+il]*sw0[s] + sfy[ib0+il]*sw0[128+s] + sb0[s];
            h1[f] = fmaxf(v, 0.f);
        }
        __syncthreads();

        float acc[8][4] = {};
        int i8 = warp * 8;
        #pragma unroll 4
        for (int s = 0; s < 128; s++) {
            float4 hA = *(const float4*)&h1[s*32 + i8];
            float4 hB = *(const float4*)&h1[s*32 + i8 + 4];
            float4 wv = *(const float4*)&W1s[s*128 + c4];
            float hv[8] = {hA.x,hA.y,hA.z,hA.w,hB.x,hB.y,hB.z,hB.w};
            #pragma unroll
            for (int ii = 0; ii < 8; ii++) {
                acc[ii][0] += hv[ii]*wv.x; acc[ii][1] += hv[ii]*wv.y;
                acc[ii][2] += hv[ii]*wv.z; acc[ii][3] += hv[ii]*wv.w;
            }
        }
        #pragma unroll
        for (int ii = 0; ii < 8; ii++) {
            float pp = 0.f;
            #pragma unroll
            for (int k = 0; k < 4; k++) {
                float h2 = fmaxf(acc[ii][k] + b1r[k], 0.f);
                pp += h2 * w2r[k];
            }
            #pragma unroll
            for (int o = 16; o > 0; o >>= 1) pp += __shfl_down_sync(0xffffffffu, pp, o);
            if (lane == 0) {
                int i = ibase0 + ib0 + i8 + ii;
                bias[(size_t)bg*(Pp*P2) + i*64 + j] = pp + b2v;
            }
        }
        __syncthreads();
    }
}

// ---------------- attention: per (b,h,i), j=64 keys ----------------
__global__ void attn_kernel(const float* __restrict__ q, const float* __restrict__ k,
                            const float* __restrict__ v, const float* __restrict__ bias,
                            float* __restrict__ out) {
    int i = blockIdx.x, h = blockIdx.y, b = blockIdx.z;
    int t = threadIdx.x;   // 64
    __shared__ float qs[64], att[64];
    qs[t] = q[(size_t)b*(Cch*Pp) + (h*64 + t)*Pp + i] * SCALE;
    __syncthreads();
    float s = bias[(size_t)(b*8 + h)*(Pp*P2) + i*64 + t];
    const float* kb = k + (size_t)b*(Cch*P2) + h*64*P2;
    #pragma unroll 8
    for (int d = 0; d < 64; d++) s += qs[d] * kb[d*64 + t];
    att[t] = s; __syncthreads();
    float m = -1e30f;
    for (int j2 = 0; j2 < 64; j2++) m = fmaxf(m, att[j2]);
    float e = __expf(s - m);
    __syncthreads();
    att[t] = e; __syncthreads();
    float sum = 0.f;
    for (int j2 = 0; j2 < 64; j2++) sum += att[j2];
    float inv = 1.f / sum;
    const float* vb = v + (size_t)b*(Cch*P2) + (h*64 + t)*P2;
    float acc = 0.f;
    #pragma unroll 8
    for (int j2 = 0; j2 < 64; j2++) acc += att[j2] * vb[j2];
    out[(size_t)b*(Cch*Pp) + (h*64 + t)*Pp + i] = acc * inv;
}

// ---------------- generic tiled GEMM: Y[o][p] = sum_c W[o][c]*A[c][p] (+bias, act, residual) ----------------
// act: 0=none, 1=exact gelu.  residual added after activation.
__global__ void gemm_kernel(const float* __restrict__ A, const float* __restrict__ W,
                            const float* __restrict__ bias, const float* __restrict__ res,
                            float* __restrict__ out, int Cin, int P, int act) {
    int b = blockIdx.z;
    int O = gridDim.y * 64;
    const float* Ab = A + (size_t)b*Cin*P;
    int p0 = blockIdx.x * 64, o0 = blockIdx.y * 64;
    __shared__ float As[64][64];
    __shared__ float Ws[64][64];   // [o][c]
    int t = threadIdx.x;
    int tp = (t & 15) * 4, to = (t >> 4) * 4;
    float acc[4][4] = {};
    for (int cc = 0; cc < Cin; cc += 64) {
        __syncthreads();
        for (int idx = t; idx < 4096; idx += 256) {
            int r = idx >> 6, q = idx & 63;
            As[r][q] = Ab[(size_t)(cc + r)*P + p0 + q];
            Ws[r][q] = W[(size_t)(o0 + r)*Cin + cc + q];
        }
        __syncthreads();
        #pragma unroll
        for (int c = 0; c < 64; c += 4) {
            float4 a[4], wv[4];
            #pragma unroll
            for (int u = 0; u < 4; u++) a[u] = *(const float4*)&As[c+u][tp];
            #pragma unroll
            for (int oi = 0; oi < 4; oi++) wv[oi] = *(const float4*)&Ws[to+oi][c];
            #pragma unroll
            for (int oi = 0; oi < 4; oi++) {
                float wf[4] = {wv[oi].x, wv[oi].y, wv[oi].z, wv[oi].w};
                #pragma unroll
                for (int u = 0; u < 4; u++) {
                    acc[oi][0] += wf[u]*a[u].x; acc[oi][1] += wf[u]*a[u].y;
                    acc[oi][2] += wf[u]*a[u].z; acc[oi][3] += wf[u]*a[u].w;
                }
            }
        }
    }
    float* ob = out + (size_t)b*O*P;
    const float* rb = res ? res + (size_t)b*O*P : nullptr;
    #pragma unroll
    for (int oi = 0; oi < 4; oi++) {
        int o = o0 + to + oi;
        float bv = bias[o];
        #pragma unroll
        for (int pj = 0; pj < 4; pj++) {
            float v2 = acc[oi][pj] + bv;
            if (act == 1) v2 = 0.5f * v2 * (1.f + erff(v2 * 0.70710678118654752f));
            if (rb) v2 += rb[(size_t)o*P + p0 + tp + pj];
            ob[(size_t)o*P + p0 + tp + pj] = v2;
        }
    }
}

// ---------------- launch ----------------
extern "C" void kernel_launch(void* const* d_in, const int* in_sizes, int n_in,
                              void* d_out, int out_size) {
    const float* x        = (const float*)d_in[0];
    const float* n1_g     = (const float*)d_in[1];
    const float* n1_b     = (const float*)d_in[2];
    const float* n2_g     = (const float*)d_in[3];
    const float* n2_b     = (const float*)d_in[4];
    const float* q_w      = (const float*)d_in[5];
    const float* k_w      = (const float*)d_in[6];
    const float* v_w      = (const float*)d_in[7];
    const float* off_dw_w = (const float*)d_in[8];
    const float* off_dw_b = (const float*)d_in[9];
    const float* off_pw_w = (const float*)d_in[10];
    const float* cpb_w0   = (const float*)d_in[11];
    const float* cpb_b0   = (const float*)d_in[12];
    const float* cpb_w1   = (const float*)d_in[13];
    const float* cpb_b1   = (const float*)d_in[14];
    const float* cpb_w2   = (const float*)d_in[15];
    const float* cpb_b2   = (const float*)d_in[16];
    const float* out_w    = (const float*)d_in[17];
    const float* out_b    = (const float*)d_in[18];
    const float* mlp_w1   = (const float*)d_in[19];
    const float* mlp_b1   = (const float*)d_in[20];
    const float* mlp_w2   = (const float*)d_in[21];
    const float* mlp_b2   = (const float*)d_in[22];
    float* out = (float*)d_out;

    float *p_xn, *p_q, *p_off1, *p_grid, *p_kv, *p_k, *p_v, *p_bias, *p_ao, *p_x1, *p_h, *p_m1;
    cudaGetSymbolAddress((void**)&p_xn,   g_xn);
    cudaGetSymbolAddress((void**)&p_q,    g_q);
    cudaGetSymbolAddress((void**)&p_off1, g_off1);
    cudaGetSymbolAddress((void**)&p_grid, g_grid);
    cudaGetSymbolAddress((void**)&p_kv,   g_kv);
    cudaGetSymbolAddress((void**)&p_k,    g_k);
    cudaGetSymbolAddress((void**)&p_v,    g_v);
    cudaGetSymbolAddress((void**)&p_bias, g_bias);
    cudaGetSymbolAddress((void**)&p_ao,   g_ao);
    cudaGetSymbolAddress((void**)&p_x1,   g_x1);
    cudaGetSymbolAddress((void**)&p_h,    g_h);
    cudaGetSymbolAddress((void**)&p_m1,   g_m1);

    // 1. batchnorm1
    bn_kernel<<<512, 256>>>(x, n1_g, n1_b, p_xn);
    // 2. q = grouped conv
    gconv_kernel<<<dim3(16, 16), 256>>>(p_xn, q_w, p_q, Pp);
    // 3. depthwise conv + gelu on q
    dwconv_kernel<<<256, 256>>>(p_q, off_dw_w, off_dw_b, p_off1);
    // 4. pointwise -> offsets -> sample grid
    offset_kernel<<<16, 64>>>(p_off1, off_pw_w, p_grid);
    // 5. bilinear sample kv
    gsample_kernel<<<256, 256>>>(p_xn, p_grid, p_kv);
    // 6. k, v grouped convs
    gconv_kernel<<<dim3(16, 1), 256>>>(p_kv, k_w, p_k, P2);
    gconv_kernel<<<dim3(16, 1), 256>>>(p_kv, v_w, p_v, P2);
    // 7. CPB bias MLP
    {
        int smem = (16384 + 4096 + 64 + 64 + 256 + 128) * 4;
        cudaFuncSetAttribute(bias_kernel, cudaFuncAttributeMaxDynamicSharedMemorySize, smem);
        bias_kernel<<<dim3(1024, 16), 128, smem>>>(p_grid, cpb_w0, cpb_b0, cpb_w1, cpb_b1,
                                                   cpb_w2, cpb_b2, p_bias);
    }
    // 8. attention
    attn_kernel<<<dim3(1024, 8, 2), 64>>>(p_q, p_k, p_v, p_bias, p_ao);
    // 9. out projection + residual with x -> x1
    gemm_kernel<<<dim3(16, 8, 2), 256>>>(p_ao, out_w, out_b, x, p_x1, 512, Pp, 0);
    // 10. batchnorm2
    bn_kernel<<<512, 256>>>(p_x1, n2_g, n2_b, p_h);
    // 11. mlp1 (512->2048) + gelu
    gemm_kernel<<<dim3(16, 32, 2), 256>>>(p_h, mlp_w1, mlp_b1, nullptr, p_m1, 512, Pp, 1);
    // 12. mlp2 (2048->512) + residual with x1 -> out
    gemm_kernel<<<dim3(16, 8, 2), 256>>>(p_m1, mlp_w2, mlp_b2, p_x1, out, 2048, Pp, 0);
}

// round 5
// speedup vs baseline: 2.2014x; 2.2014x over previous
#include <cuda_runtime.h>
#include <cuda_bf16.h>
#include <stdint.h>
#include <math.h>

// Problem constants
#define Bsz 2
#define Cch 512
#define Gg  8
#define Cg  64
#define Pp  1024          // H*W
#define P2  64            // H2*W2
#define SCALE 0.125f

// ---------------- scratch (static device globals; no allocation) ----------------
__device__ float g_xn  [Bsz*Cch*Pp];
__device__ float g_q   [Bsz*Cch*Pp];
__device__ float g_off1[16*Cg*P2];
__device__ float g_grid[16*P2*2];
__device__ float g_kv  [16*Cg*P2];
__device__ float g_k   [Bsz*Cch*P2];
__device__ float g_v   [Bsz*Cch*P2];
__device__ float g_bias[16*Pp*P2];
__device__ float g_ao  [Bsz*Cch*Pp];
__device__ float g_x1  [Bsz*Cch*Pp];
__device__ float g_h   [Bsz*Cch*Pp];
__device__ float g_m1  [Bsz*2048*Pp];

// ---------------- batchnorm ----------------
__global__ void bn_kernel(const float* __restrict__ x, const float* __restrict__ g,
                          const float* __restrict__ b, float* __restrict__ y) {
    int c = blockIdx.x, t = threadIdx.x;
    __shared__ float ssum[256], ssq[256];
    float s = 0.f, q = 0.f;
    for (int idx = t; idx < 2048; idx += 256) {
        int bb = idx >> 10, p = idx & 1023;
        float v = x[bb*(Cch*Pp) + c*Pp + p];
        s += v; q += v*v;
    }
    ssum[t] = s; ssq[t] = q; __syncthreads();
    for (int o = 128; o > 0; o >>= 1) {
        if (t < o) { ssum[t] += ssum[t+o]; ssq[t] += ssq[t+o]; }
        __syncthreads();
    }
    float m  = ssum[0] * (1.f/2048.f);
    float var = ssq[0] * (1.f/2048.f) - m*m;
    float rs = rsqrtf(var + 1e-5f);
    float gg = g[c] * rs;
    float bb2 = b[c] - m * gg;
    for (int idx = t; idx < 2048; idx += 256) {
        int bb = idx >> 10, p = idx & 1023;
        y[bb*(Cch*Pp) + c*Pp + p] = x[bb*(Cch*Pp) + c*Pp + p] * gg + bb2;
    }
}

// ---------------- grouped 1x1 conv ----------------
__global__ void gconv_kernel(const float* __restrict__ in, const float* __restrict__ w,
                             float* __restrict__ out, int P) {
    int bg = blockIdx.x, pt = blockIdx.y;
    int grp = bg & 7;
    const float* A  = in + (size_t)bg*Cg*P + pt*64;
    const float* Wg = w + grp*4096;
    float* O        = out + (size_t)bg*Cg*P + pt*64;
    __shared__ float As[64][64];
    __shared__ float Ws[64][64];
    int t = threadIdx.x;
    for (int idx = t; idx < 4096; idx += 256) {
        int r = idx >> 6, q = idx & 63;
        As[r][q] = A[r*P + q];
        ((float*)Ws)[idx] = Wg[idx];
    }
    __syncthreads();
    int tp = (t & 15) * 4, to = (t >> 4) * 4;
    float acc[4][4] = {};
    #pragma unroll
    for (int c = 0; c < 64; c += 4) {
        float4 a[4], wv[4];
        #pragma unroll
        for (int u = 0; u < 4; u++) a[u] = *(const float4*)&As[c+u][tp];
        #pragma unroll
        for (int oi = 0; oi < 4; oi++) wv[oi] = *(const float4*)&Ws[to+oi][c];
        #pragma unroll
        for (int oi = 0; oi < 4; oi++) {
            float wf[4] = {wv[oi].x, wv[oi].y, wv[oi].z, wv[oi].w};
            #pragma unroll
            for (int u = 0; u < 4; u++) {
                acc[oi][0] += wf[u]*a[u].x; acc[oi][1] += wf[u]*a[u].y;
                acc[oi][2] += wf[u]*a[u].z; acc[oi][3] += wf[u]*a[u].w;
            }
        }
    }
    #pragma unroll
    for (int oi = 0; oi < 4; oi++)
        #pragma unroll
        for (int pj = 0; pj < 4; pj++)
            O[(to+oi)*P + tp+pj] = acc[oi][pj];
}

// ---------------- depthwise 6x6 stride-4 pad-1 conv + gelu ----------------
__global__ void dwconv_kernel(const float* __restrict__ q, const float* __restrict__ dw,
                              const float* __restrict__ db, float* __restrict__ out) {
    int idx = blockIdx.x*blockDim.x + threadIdx.x;
    if (idx >= 16*Cg*P2) return;
    int p = idx & 63, c = (idx >> 6) & 63, bg = idx >> 12;
    int oy = p >> 3, ox = p & 7;
    float acc = db[c];
    const float* ip = q + (size_t)bg*Cg*Pp + c*Pp;
    const float* wp = dw + c*36;
    #pragma unroll
    for (int ky = 0; ky < 6; ky++) {
        int iy = oy*4 - 1 + ky;
        if (iy < 0 || iy >= 32) continue;
        #pragma unroll
        for (int kx = 0; kx < 6; kx++) {
            int ix = ox*4 - 1 + kx;
            if (ix < 0 || ix >= 32) continue;
            acc += ip[iy*32 + ix] * wp[ky*6 + kx];
        }
    }
    out[idx] = 0.5f * acc * (1.f + erff(acc * 0.70710678118654752f));
}

// ---------------- pointwise 64->2, tanh*4, sample grid ----------------
__global__ void offset_kernel(const float* __restrict__ off1, const float* __restrict__ pw,
                              float* __restrict__ grid) {
    int bg = blockIdx.x, p = threadIdx.x;
    float s0 = 0.f, s1 = 0.f;
    const float* base = off1 + bg*(Cg*P2);
    for (int c = 0; c < 64; c++) {
        float v = base[c*64 + p];
        s0 += v * pw[c];
        s1 += v * pw[64 + c];
    }
    float ox = tanhf(s0) * 4.f, oy = tanhf(s1) * 4.f;
    float gx = (float)(p & 7), gy = (float)(p >> 3);
    float vx = 2.f * (gx + ox) * (1.f/7.f) - 1.f;
    float vy = 2.f * (gy + oy) * (1.f/7.f) - 1.f;
    grid[bg*128 + p*2]     = vx;
    grid[bg*128 + p*2 + 1] = vy;
}

// ---------------- bilinear grid sample ----------------
__global__ void gsample_kernel(const float* __restrict__ xn, const float* __restrict__ grid,
                               float* __restrict__ kv) {
    int idx = blockIdx.x*blockDim.x + threadIdx.x;
    if (idx >= 16*Cg*P2) return;
    int p = idx & 63, c = (idx >> 6) & 63, bg = idx >> 12;
    float vx = grid[bg*128 + p*2], vy = grid[bg*128 + p*2 + 1];
    float x = ((vx + 1.f) * 32.f - 1.f) * 0.5f;
    float y = ((vy + 1.f) * 32.f - 1.f) * 0.5f;
    float x0f = floorf(x), y0f = floorf(y);
    int x0 = (int)x0f, y0 = (int)y0f;
    float wx = x - x0f, wy = y - y0f;
    const float* im = xn + (size_t)bg*Cg*Pp + c*Pp;
    float v00 = (x0   >= 0 && x0   < 32 && y0   >= 0 && y0   < 32) ? im[y0*32 + x0]       : 0.f;
    float v10 = (x0+1 >= 0 && x0+1 < 32 && y0   >= 0 && y0   < 32) ? im[y0*32 + x0+1]     : 0.f;
    float v01 = (x0   >= 0 && x0   < 32 && y0+1 >= 0 && y0+1 < 32) ? im[(y0+1)*32 + x0]   : 0.f;
    float v11 = (x0+1 >= 0 && x0+1 < 32 && y0+1 >= 0 && y0+1 < 32) ? im[(y0+1)*32 + x0+1] : 0.f;
    kv[idx] = v00*(1.f-wx)*(1.f-wy) + v10*wx*(1.f-wy) + v01*(1.f-wx)*wy + v11*wx*wy;
}

// ======================= CPB bias MLP — bf16 tensor-core version =======================
#define BPAD 136   // bf16 row stride (halfs)

__device__ __forceinline__ void ldsm4(uint32_t addr, uint32_t& r0, uint32_t& r1,
                                      uint32_t& r2, uint32_t& r3) {
    asm volatile("ldmatrix.sync.aligned.m8n8.x4.shared.b16 {%0,%1,%2,%3}, [%4];"
                 : "=r"(r0), "=r"(r1), "=r"(r2), "=r"(r3) : "r"(addr));
}
__device__ __forceinline__ void mma_bf16(float* c, const uint32_t* a, uint32_t b0, uint32_t b1) {
    asm volatile("mma.sync.aligned.m16n8k16.row.col.f32.bf16.bf16.f32 "
                 "{%0,%1,%2,%3}, {%4,%5,%6,%7}, {%8,%9}, {%0,%1,%2,%3};"
                 : "+f"(c[0]), "+f"(c[1]), "+f"(c[2]), "+f"(c[3])
                 : "r"(a[0]), "r"(a[1]), "r"(a[2]), "r"(a[3]), "r"(b0), "r"(b1));
}

__global__ void bias_mma_kernel(const float* __restrict__ grid,
                                const float* __restrict__ w0, const float* __restrict__ b0,
                                const float* __restrict__ w1, const float* __restrict__ b1,
                                const float* __restrict__ w2, const float* __restrict__ b2,
                                float* __restrict__ bias) {
    extern __shared__ unsigned char smraw[];
    __nv_bfloat16* W1Ts = (__nv_bfloat16*)smraw;           // [n][s] 128 x BPAD
    __nv_bfloat16* H1s  = W1Ts + 128*BPAD;                 // [i][s] 128 x BPAD
    float* w0s = (float*)(H1s + 128*BPAD);                 // 256
    float* b0s = w0s + 256;                                // 128
    float* b1s = b0s + 128;                                // 128
    float* w2s = b1s + 128;                                // 128

    int t = threadIdx.x;
    int lane = t & 31, warp = t >> 5;
    int ih = blockIdx.x, j = blockIdx.y, bg = blockIdx.z;

    // stage weights
    for (int idx = t; idx < 16384; idx += 128) {
        int s = idx >> 7, n = idx & 127;
        W1Ts[n*BPAD + s] = __float2bfloat16(w1[idx]);
    }
    for (int idx = t; idx < 256; idx += 128) w0s[idx] = w0[idx];
    b0s[t] = b0[t];
    b1s[t] = b1[t];
    w2s[t] = w2[t];
    float kvx = grid[bg*128 + j*2], kvy = grid[bg*128 + j*2 + 1];
    float b2v = b2[0];
    __syncthreads();

    uint32_t h1base = (uint32_t)__cvta_generic_to_shared(H1s);
    uint32_t w1base = (uint32_t)__cvta_generic_to_shared(W1Ts);
    size_t bgbase = (size_t)bg * (Pp*P2);
    int m0 = 32*warp;

    for (int it = 0; it < 4; it++) {
        int i0 = ih*512 + it*128;

        // build H1 row t
        {
            int i = i0 + t;
            float qx = 2.f * (float)(i & 31) * (1.f/31.f) - 1.f;
            float qy = 2.f * (float)(i >> 5) * (1.f/31.f) - 1.f;
            float px = qx - kvx, py = qy - kvy;
            float fx = copysignf(log1pf(fabsf(px)), px);
            float fy = copysignf(log1pf(fabsf(py)), py);
            __nv_bfloat162* rowp = (__nv_bfloat162*)(H1s + t*BPAD);
            #pragma unroll 8
            for (int s = 0; s < 128; s += 2) {
                float h0 = fmaxf(fmaf(fy, w0s[128+s],   fmaf(fx, w0s[s],   b0s[s])),   0.f);
                float h1v= fmaxf(fmaf(fy, w0s[128+s+1], fmaf(fx, w0s[s+1], b0s[s+1])), 0.f);
                rowp[s>>1] = __floats2bfloat162_rn(h0, h1v);
            }
        }
        __syncthreads();

        float rs[4] = {0.f, 0.f, 0.f, 0.f};
        int arow = (lane & 7) + ((lane >> 3) & 1) * 8;
        int acolq = (lane >> 4) * 8;
        int bn_off = (lane >> 4) * 8 + (lane & 7);
        int bcol = ((lane >> 3) & 1) * 8;

        for (int nh = 0; nh < 2; nh++) {
            float c[2][8][4] = {};
            #pragma unroll
            for (int k8 = 0; k8 < 8; k8++) {
                int k0 = k8 * 16;
                uint32_t A[2][4];
                #pragma unroll
                for (int mt = 0; mt < 2; mt++) {
                    int row = m0 + mt*16 + arow;
                    uint32_t addr = h1base + (uint32_t)(row*BPAD + k0 + acolq) * 2u;
                    ldsm4(addr, A[mt][0], A[mt][1], A[mt][2], A[mt][3]);
                }
                uint32_t Bf[4][4];
                #pragma unroll
                for (int np = 0; np < 4; np++) {
                    int n = nh*64 + np*16 + bn_off;
                    uint32_t addr = w1base + (uint32_t)(n*BPAD + k0 + bcol) * 2u;
                    ldsm4(addr, Bf[np][0], Bf[np][1], Bf[np][2], Bf[np][3]);
                }
                #pragma unroll
                for (int nt = 0; nt < 8; nt++) {
                    uint32_t bb0 = Bf[nt>>1][(nt&1)*2], bb1 = Bf[nt>>1][(nt&1)*2+1];
                    mma_bf16(c[0][nt], A[0], bb0, bb1);
                    mma_bf16(c[1][nt], A[1], bb0, bb1);
                }
            }
            #pragma unroll
            for (int nt = 0; nt < 8; nt++) {
                int n = nh*64 + nt*8 + 2*(lane & 3);
                float b1a = b1s[n], b1b = b1s[n+1];
                float w2a = w2s[n], w2b = w2s[n+1];
                #pragma unroll
                for (int mt = 0; mt < 2; mt++) {
                    rs[mt*2+0] += fmaxf(c[mt][nt][0]+b1a, 0.f)*w2a + fmaxf(c[mt][nt][1]+b1b, 0.f)*w2b;
                    rs[mt*2+1] += fmaxf(c[mt][nt][2]+b1a, 0.f)*w2a + fmaxf(c[mt][nt][3]+b1b, 0.f)*w2b;
                }
            }
        }
        #pragma unroll
        for (int k = 0; k < 4; k++) {
            rs[k] += __shfl_xor_sync(0xffffffffu, rs[k], 1);
            rs[k] += __shfl_xor_sync(0xffffffffu, rs[k], 2);
        }
        if ((lane & 3) == 0) {
            int gid = lane >> 2;
            #pragma unroll
            for (int mt = 0; mt < 2; mt++) {
                int i1 = i0 + m0 + mt*16 + gid;
                bias[bgbase + (size_t)i1*64 + j]     = rs[mt*2+0] + b2v;
                bias[bgbase + (size_t)(i1+8)*64 + j] = rs[mt*2+1] + b2v;
            }
        }
        __syncthreads();
    }
}

// ---------------- attention ----------------
__global__ void attn_kernel(const float* __restrict__ q, const float* __restrict__ k,
                            const float* __restrict__ v, const float* __restrict__ bias,
                            float* __restrict__ out) {
    int i = blockIdx.x, h = blockIdx.y, b = blockIdx.z;
    int t = threadIdx.x;
    __shared__ float qs[64], att[64];
    qs[t] = q[(size_t)b*(Cch*Pp) + (h*64 + t)*Pp + i] * SCALE;
    __syncthreads();
    float s = bias[(size_t)(b*8 + h)*(Pp*P2) + i*64 + t];
    const float* kb = k + (size_t)b*(Cch*P2) + h*64*P2;
    #pragma unroll 8
    for (int d = 0; d < 64; d++) s += qs[d] * kb[d*64 + t];
    att[t] = s; __syncthreads();
    float m = -1e30f;
    for (int j2 = 0; j2 < 64; j2++) m = fmaxf(m, att[j2]);
    float e = __expf(s - m);
    __syncthreads();
    att[t] = e; __syncthreads();
    float sum = 0.f;
    for (int j2 = 0; j2 < 64; j2++) sum += att[j2];
    float inv = 1.f / sum;
    const float* vb = v + (size_t)b*(Cch*P2) + (h*64 + t)*P2;
    float acc = 0.f;
    #pragma unroll 8
    for (int j2 = 0; j2 < 64; j2++) acc += att[j2] * vb[j2];
    out[(size_t)b*(Cch*Pp) + (h*64 + t)*Pp + i] = acc * inv;
}

// ======================= tf32 tensor-core GEMM =======================
__device__ __forceinline__ uint32_t f2tf32(float v) {
    uint32_t u;
    asm("cvt.rna.tf32.f32 %0, %1;" : "=r"(u) : "f"(v));
    return u;
}
__device__ __forceinline__ void mma_tf32(float* c, const uint32_t* a, uint32_t b0, uint32_t b1) {
    asm volatile("mma.sync.aligned.m16n8k8.row.col.f32.tf32.tf32.f32 "
                 "{%0,%1,%2,%3}, {%4,%5,%6,%7}, {%8,%9}, {%0,%1,%2,%3};"
                 : "+f"(c[0]), "+f"(c[1]), "+f"(c[2]), "+f"(c[3])
                 : "r"(a[0]), "r"(a[1]), "r"(a[2]), "r"(a[3]), "r"(b0), "r"(b1));
}

__global__ void gemm_tf32_kernel(const float* __restrict__ A, const float* __restrict__ W,
                                 const float* __restrict__ bias, const float* __restrict__ res,
                                 float* __restrict__ out, int Cin, int act) {
    const int P = 1024;
    int b = blockIdx.z;
    int O = gridDim.y * 128;
    int p0 = blockIdx.x * 128, o0 = blockIdx.y * 128;
    const float* Ab = A + (size_t)b*Cin*P;

    __shared__ uint32_t Wt[128][36];   // [o][c] tf32
    __shared__ uint32_t Xt[32][136];   // [c][p] tf32

    int t = threadIdx.x;
    int lane = t & 31, warp = t >> 5;
    int gid = lane >> 2, ctid = lane & 3;
    int m0w = (warp >> 1) * 32, n0w = (warp & 1) * 64;

    float c[2][8][4] = {};

    for (int cc = 0; cc < Cin; cc += 32) {
        __syncthreads();
        #pragma unroll 4
        for (int idx = t; idx < 4096; idx += 256) {
            int r = idx >> 5, q = idx & 31;
            Wt[r][q] = f2tf32(W[(size_t)(o0 + r)*Cin + cc + q]);
        }
        #pragma unroll 4
        for (int idx = t; idx < 4096; idx += 256) {
            int r = idx >> 7, q = idx & 127;
            Xt[r][q] = f2tf32(Ab[(size_t)(cc + r)*P + p0 + q]);
        }
        __syncthreads();
        #pragma unroll
        for (int k0 = 0; k0 < 32; k0 += 8) {
            uint32_t a[2][4];
            #pragma unroll
            for (int mt = 0; mt < 2; mt++) {
                int row = m0w + mt*16;
                a[mt][0] = Wt[row + gid    ][k0 + ctid];
                a[mt][1] = Wt[row + 8 + gid][k0 + ctid];
                a[mt][2] = Wt[row + gid    ][k0 + ctid + 4];
                a[mt][3] = Wt[row + 8 + gid][k0 + ctid + 4];
            }
            #pragma unroll
            for (int nt = 0; nt < 8; nt++) {
                int n = n0w + nt*8 + gid;
                uint32_t b0v = Xt[k0 + ctid    ][n];
                uint32_t b1v = Xt[k0 + ctid + 4][n];
                mma_tf32(c[0][nt], a[0], b0v, b1v);
                mma_tf32(c[1][nt], a[1], b0v, b1v);
            }
        }
    }

    float* ob = out + (size_t)b*O*P;
    const float* rb = res ? res + (size_t)b*O*P : nullptr;
    #pragma unroll
    for (int mt = 0; mt < 2; mt++) {
        #pragma unroll
        for (int half = 0; half < 2; half++) {
            int o = o0 + m0w + mt*16 + gid + half*8;
            float bv = bias[o];
            #pragma unroll
            for (int nt = 0; nt < 8; nt++) {
                int p = p0 + n0w + nt*8 + 2*ctid;
                float v0 = c[mt][nt][half*2+0] + bv;
                float v1 = c[mt][nt][half*2+1] + bv;
                if (act == 1) {
                    v0 = 0.5f * v0 * (1.f + erff(v0 * 0.70710678118654752f));
                    v1 = 0.5f * v1 * (1.f + erff(v1 * 0.70710678118654752f));
                }
                if (rb) {
                    const float2 rv = *(const float2*)&rb[(size_t)o*P + p];
                    v0 += rv.x; v1 += rv.y;
                }
                float2 st; st.x = v0; st.y = v1;
                *(float2*)&ob[(size_t)o*P + p] = st;
            }
        }
    }
}

// ---------------- launch ----------------
extern "C" void kernel_launch(void* const* d_in, const int* in_sizes, int n_in,
                              void* d_out, int out_size) {
    const float* x        = (const float*)d_in[0];
    const float* n1_g     = (const float*)d_in[1];
    const float* n1_b     = (const float*)d_in[2];
    const float* n2_g     = (const float*)d_in[3];
    const float* n2_b     = (const float*)d_in[4];
    const float* q_w      = (const float*)d_in[5];
    const float* k_w      = (const float*)d_in[6];
    const float* v_w      = (const float*)d_in[7];
    const float* off_dw_w = (const float*)d_in[8];
    const float* off_dw_b = (const float*)d_in[9];
    const float* off_pw_w = (const float*)d_in[10];
    const float* cpb_w0   = (const float*)d_in[11];
    const float* cpb_b0   = (const float*)d_in[12];
    const float* cpb_w1   = (const float*)d_in[13];
    const float* cpb_b1   = (const float*)d_in[14];
    const float* cpb_w2   = (const float*)d_in[15];
    const float* cpb_b2   = (const float*)d_in[16];
    const float* out_w    = (const float*)d_in[17];
    const float* out_b    = (const float*)d_in[18];
    const float* mlp_w1   = (const float*)d_in[19];
    const float* mlp_b1   = (const float*)d_in[20];
    const float* mlp_w2   = (const float*)d_in[21];
    const float* mlp_b2   = (const float*)d_in[22];
    float* out = (float*)d_out;

    float *p_xn, *p_q, *p_off1, *p_grid, *p_kv, *p_k, *p_v, *p_bias, *p_ao, *p_x1, *p_h, *p_m1;
    cudaGetSymbolAddress((void**)&p_xn,   g_xn);
    cudaGetSymbolAddress((void**)&p_q,    g_q);
    cudaGetSymbolAddress((void**)&p_off1, g_off1);
    cudaGetSymbolAddress((void**)&p_grid, g_grid);
    cudaGetSymbolAddress((void**)&p_kv,   g_kv);
    cudaGetSymbolAddress((void**)&p_k,    g_k);
    cudaGetSymbolAddress((void**)&p_v,    g_v);
    cudaGetSymbolAddress((void**)&p_bias, g_bias);
    cudaGetSymbolAddress((void**)&p_ao,   g_ao);
    cudaGetSymbolAddress((void**)&p_x1,   g_x1);
    cudaGetSymbolAddress((void**)&p_h,    g_h);
    cudaGetSymbolAddress((void**)&p_m1,   g_m1);

    bn_kernel<<<512, 256>>>(x, n1_g, n1_b, p_xn);
    gconv_kernel<<<dim3(16, 16), 256>>>(p_xn, q_w, p_q, Pp);
    dwconv_kernel<<<256, 256>>>(p_q, off_dw_w, off_dw_b, p_off1);
    offset_kernel<<<16, 64>>>(p_off1, off_pw_w, p_grid);
    gsample_kernel<<<256, 256>>>(p_xn, p_grid, p_kv);
    gconv_kernel<<<dim3(16, 1), 256>>>(p_kv, k_w, p_k, P2);
    gconv_kernel<<<dim3(16, 1), 256>>>(p_kv, v_w, p_v, P2);
    {
        int smem = 2*128*BPAD*2 + (256 + 128 + 128 + 128)*4;
        cudaFuncSetAttribute(bias_mma_kernel, cudaFuncAttributeMaxDynamicSharedMemorySize, smem);
        bias_mma_kernel<<<dim3(2, 64, 16), 128, smem>>>(p_grid, cpb_w0, cpb_b0, cpb_w1, cpb_b1,
                                                        cpb_w2, cpb_b2, p_bias);
    }
    attn_kernel<<<dim3(1024, 8, 2), 64>>>(p_q, p_k, p_v, p_bias, p_ao);
    gemm_tf32_kernel<<<dim3(8, 4, 2), 256>>>(p_ao, out_w, out_b, x, p_x1, 512, 0);
    bn_kernel<<<512, 256>>>(p_x1, n2_g, n2_b, p_h);
    gemm_tf32_kernel<<<dim3(8, 16, 2), 256>>>(p_h, mlp_w1, mlp_b1, nullptr, p_m1, 512, 1);
    gemm_tf32_kernel<<<dim3(8, 4, 2), 256>>>(p_m1, mlp_w2, mlp_b2, p_x1, out, 2048, 0);
}

// round 6
// speedup vs baseline: 3.0033x; 1.3643x over previous
#include <cuda_runtime.h>
#include <cuda_bf16.h>
#include <stdint.h>
#include <math.h>

// Problem constants
#define Bsz 2
#define Cch 512
#define Gg  8
#define Cg  64
#define Pp  1024          // H*W
#define P2  64            // H2*W2
#define SCALE 0.125f

// ---------------- scratch (static device globals; no allocation) ----------------
__device__ float g_xn  [Bsz*Cch*Pp];
__device__ float g_q   [Bsz*Cch*Pp];
__device__ float g_grid[16*P2*2];
__device__ float g_kv  [16*Cg*P2];
__device__ float g_k   [Bsz*Cch*P2];
__device__ float g_v   [Bsz*Cch*P2];
__device__ float g_bias[16*Pp*P2];
__device__ float g_ao  [Bsz*Cch*Pp];
__device__ float g_x1  [Bsz*Cch*Pp];
__device__ float g_h   [Bsz*Cch*Pp];
__device__ float g_m1  [Bsz*2048*Pp];
__device__ __nv_bfloat16 g_w1t[128*128];   // W1^T pre-converted to bf16, [n][s]

// ---------------- batchnorm ----------------
__global__ void bn_kernel(const float* __restrict__ x, const float* __restrict__ g,
                          const float* __restrict__ b, float* __restrict__ y) {
    int c = blockIdx.x, t = threadIdx.x;
    __shared__ float ssum[256], ssq[256];
    float s = 0.f, q = 0.f;
    for (int idx = t; idx < 2048; idx += 256) {
        int bb = idx >> 10, p = idx & 1023;
        float v = x[bb*(Cch*Pp) + c*Pp + p];
        s += v; q += v*v;
    }
    ssum[t] = s; ssq[t] = q; __syncthreads();
    for (int o = 128; o > 0; o >>= 1) {
        if (t < o) { ssum[t] += ssum[t+o]; ssq[t] += ssq[t+o]; }
        __syncthreads();
    }
    float m  = ssum[0] * (1.f/2048.f);
    float var = ssq[0] * (1.f/2048.f) - m*m;
    float rs = rsqrtf(var + 1e-5f);
    float gg = g[c] * rs;
    float bb2 = b[c] - m * gg;
    for (int idx = t; idx < 2048; idx += 256) {
        int bb = idx >> 10, p = idx & 1023;
        y[bb*(Cch*Pp) + c*Pp + p] = x[bb*(Cch*Pp) + c*Pp + p] * gg + bb2;
    }
}

// ---------------- grouped 1x1 conv (q) ----------------
__global__ void gconv_kernel(const float* __restrict__ in, const float* __restrict__ w,
                             float* __restrict__ out, int P) {
    int bg = blockIdx.x, pt = blockIdx.y;
    int grp = bg & 7;
    const float* A  = in + (size_t)bg*Cg*P + pt*64;
    const float* Wg = w + grp*4096;
    float* O        = out + (size_t)bg*Cg*P + pt*64;
    __shared__ float As[64][64];
    __shared__ float Ws[64][64];
    int t = threadIdx.x;
    for (int idx = t; idx < 4096; idx += 256) {
        int r = idx >> 6, q = idx & 63;
        As[r][q] = A[r*P + q];
        ((float*)Ws)[idx] = Wg[idx];
    }
    __syncthreads();
    int tp = (t & 15) * 4, to = (t >> 4) * 4;
    float acc[4][4] = {};
    #pragma unroll
    for (int c = 0; c < 64; c += 4) {
        float4 a[4], wv[4];
        #pragma unroll
        for (int u = 0; u < 4; u++) a[u] = *(const float4*)&As[c+u][tp];
        #pragma unroll
        for (int oi = 0; oi < 4; oi++) wv[oi] = *(const float4*)&Ws[to+oi][c];
        #pragma unroll
        for (int oi = 0; oi < 4; oi++) {
            float wf[4] = {wv[oi].x, wv[oi].y, wv[oi].z, wv[oi].w};
            #pragma unroll
            for (int u = 0; u < 4; u++) {
                acc[oi][0] += wf[u]*a[u].x; acc[oi][1] += wf[u]*a[u].y;
                acc[oi][2] += wf[u]*a[u].z; acc[oi][3] += wf[u]*a[u].w;
            }
        }
    }
    #pragma unroll
    for (int oi = 0; oi < 4; oi++)
        #pragma unroll
        for (int pj = 0; pj < 4; pj++)
            O[(to+oi)*P + tp+pj] = acc[oi][pj];
}

// ---------------- grouped 1x1 conv producing BOTH k and v (shared A staging) ----------------
__global__ void gconv_kv_kernel(const float* __restrict__ in, const float* __restrict__ kw,
                                const float* __restrict__ vw, float* __restrict__ kout,
                                float* __restrict__ vout) {
    const int P = P2;
    int bg = blockIdx.x;
    int grp = bg & 7;
    const float* A = in + (size_t)bg*Cg*P;
    __shared__ float As[64][64];
    __shared__ float Wk[64][64];
    __shared__ float Wv[64][64];
    int t = threadIdx.x;
    for (int idx = t; idx < 4096; idx += 256) {
        ((float*)As)[idx] = A[idx];
        ((float*)Wk)[idx] = kw[grp*4096 + idx];
        ((float*)Wv)[idx] = vw[grp*4096 + idx];
    }
    __syncthreads();
    int tp = (t & 15) * 4, to = (t >> 4) * 4;
    float ak[4][4] = {}, av[4][4] = {};
    #pragma unroll
    for (int c = 0; c < 64; c += 4) {
        float4 a[4], wk[4], wv[4];
        #pragma unroll
        for (int u = 0; u < 4; u++) a[u] = *(const float4*)&As[c+u][tp];
        #pragma unroll
        for (int oi = 0; oi < 4; oi++) {
            wk[oi] = *(const float4*)&Wk[to+oi][c];
            wv[oi] = *(const float4*)&Wv[to+oi][c];
        }
        #pragma unroll
        for (int oi = 0; oi < 4; oi++) {
            float kf[4] = {wk[oi].x, wk[oi].y, wk[oi].z, wk[oi].w};
            float vf[4] = {wv[oi].x, wv[oi].y, wv[oi].z, wv[oi].w};
            #pragma unroll
            for (int u = 0; u < 4; u++) {
                ak[oi][0] += kf[u]*a[u].x; ak[oi][1] += kf[u]*a[u].y;
                ak[oi][2] += kf[u]*a[u].z; ak[oi][3] += kf[u]*a[u].w;
                av[oi][0] += vf[u]*a[u].x; av[oi][1] += vf[u]*a[u].y;
                av[oi][2] += vf[u]*a[u].z; av[oi][3] += vf[u]*a[u].w;
            }
        }
    }
    float* KO = kout + (size_t)bg*Cg*P;
    float* VO = vout + (size_t)bg*Cg*P;
    #pragma unroll
    for (int oi = 0; oi < 4; oi++)
        #pragma unroll
        for (int pj = 0; pj < 4; pj++) {
            KO[(to+oi)*P + tp+pj] = ak[oi][pj];
            VO[(to+oi)*P + tp+pj] = av[oi][pj];
        }
}

// ---------------- fused: depthwise conv+gelu -> pointwise offsets -> grid -> bilinear sample ----------------
// one block per bg, 256 threads.
__global__ void offs_fused_kernel(const float* __restrict__ q, const float* __restrict__ dw,
                                  const float* __restrict__ db, const float* __restrict__ pw,
                                  const float* __restrict__ xn, float* __restrict__ grid,
                                  float* __restrict__ kv) {
    __shared__ float off1s[Cg*P2];    // [c][p]
    __shared__ float sgrid[P2*2];
    int bg = blockIdx.x, t = threadIdx.x;

    // stage 1: depthwise 6x6 s4 p1 conv + bias + exact gelu -> smem
    for (int idx = t; idx < Cg*P2; idx += 256) {
        int p = idx & 63, c = idx >> 6;
        int oy = p >> 3, ox = p & 7;
        float acc = db[c];
        const float* ip = q + (size_t)bg*Cg*Pp + c*Pp;
        const float* wp = dw + c*36;
        #pragma unroll
        for (int ky = 0; ky < 6; ky++) {
            int iy = oy*4 - 1 + ky;
            if (iy < 0 || iy >= 32) continue;
            #pragma unroll
            for (int kx = 0; kx < 6; kx++) {
                int ix = ox*4 - 1 + kx;
                if (ix < 0 || ix >= 32) continue;
                acc += ip[iy*32 + ix] * wp[ky*6 + kx];
            }
        }
        off1s[idx] = 0.5f * acc * (1.f + erff(acc * 0.70710678118654752f));
    }
    __syncthreads();

    // stage 2: pointwise 64->2, tanh*4, build normalized grid
    if (t < 64) {
        int p = t;
        float s0 = 0.f, s1 = 0.f;
        #pragma unroll 8
        for (int c = 0; c < 64; c++) {
            float v = off1s[c*64 + p];
            s0 += v * pw[c];
            s1 += v * pw[64 + c];
        }
        float ox = tanhf(s0) * 4.f, oy = tanhf(s1) * 4.f;
        float gx = (float)(p & 7), gy = (float)(p >> 3);
        float vx = 2.f * (gx + ox) * (1.f/7.f) - 1.f;
        float vy = 2.f * (gy + oy) * (1.f/7.f) - 1.f;
        sgrid[p*2]   = vx;
        sgrid[p*2+1] = vy;
        grid[bg*128 + p*2]   = vx;
        grid[bg*128 + p*2+1] = vy;
    }
    __syncthreads();

    // stage 3: bilinear sample
    for (int idx = t; idx < Cg*P2; idx += 256) {
        int p = idx & 63, c = idx >> 6;
        float vx = sgrid[p*2], vy = sgrid[p*2+1];
        float x = ((vx + 1.f) * 32.f - 1.f) * 0.5f;
        float y = ((vy + 1.f) * 32.f - 1.f) * 0.5f;
        float x0f = floorf(x), y0f = floorf(y);
        int x0 = (int)x0f, y0 = (int)y0f;
        float wx = x - x0f, wy = y - y0f;
        const float* im = xn + (size_t)bg*Cg*Pp + c*Pp;
        float v00 = (x0   >= 0 && x0   < 32 && y0   >= 0 && y0   < 32) ? im[y0*32 + x0]       : 0.f;
        float v10 = (x0+1 >= 0 && x0+1 < 32 && y0   >= 0 && y0   < 32) ? im[y0*32 + x0+1]     : 0.f;
        float v01 = (x0   >= 0 && x0   < 32 && y0+1 >= 0 && y0+1 < 32) ? im[(y0+1)*32 + x0]   : 0.f;
        float v11 = (x0+1 >= 0 && x0+1 < 32 && y0+1 >= 0 && y0+1 < 32) ? im[(y0+1)*32 + x0+1] : 0.f;
        kv[(size_t)bg*Cg*P2 + idx] =
            v00*(1.f-wx)*(1.f-wy) + v10*wx*(1.f-wy) + v01*(1.f-wx)*wy + v11*wx*wy;
    }
}

// ---------------- one-time W1 -> bf16 transpose/convert ----------------
__global__ void w1cvt_kernel(const float* __restrict__ w1) {
    int idx = blockIdx.x*256 + threadIdx.x;  // 16384
    int s = idx >> 7, n = idx & 127;
    g_w1t[n*128 + s] = __float2bfloat16(w1[idx]);
}

// ======================= CPB bias MLP — bf16 tensor-core version =======================
#define BPAD 136   // bf16 row stride (halfs)

__device__ __forceinline__ void ldsm4(uint32_t addr, uint32_t& r0, uint32_t& r1,
                                      uint32_t& r2, uint32_t& r3) {
    asm volatile("ldmatrix.sync.aligned.m8n8.x4.shared.b16 {%0,%1,%2,%3}, [%4];"
                 : "=r"(r0), "=r"(r1), "=r"(r2), "=r"(r3) : "r"(addr));
}
__device__ __forceinline__ void mma_bf16(float* c, const uint32_t* a, uint32_t b0, uint32_t b1) {
    asm volatile("mma.sync.aligned.m16n8k16.row.col.f32.bf16.bf16.f32 "
                 "{%0,%1,%2,%3}, {%4,%5,%6,%7}, {%8,%9}, {%0,%1,%2,%3};"
                 : "+f"(c[0]), "+f"(c[1]), "+f"(c[2]), "+f"(c[3])
                 : "r"(a[0]), "r"(a[1]), "r"(a[2]), "r"(a[3]), "r"(b0), "r"(b1));
}

__global__ void bias_mma_kernel(const float* __restrict__ grid,
                                const float* __restrict__ w0, const float* __restrict__ b0,
                                const __nv_bfloat16* __restrict__ w1t,
                                const float* __restrict__ b1,
                                const float* __restrict__ w2, const float* __restrict__ b2,
                                float* __restrict__ bias) {
    extern __shared__ unsigned char smraw[];
    __nv_bfloat16* W1Ts = (__nv_bfloat16*)smraw;           // [n][s] 128 x BPAD
    __nv_bfloat16* H1s  = W1Ts + 128*BPAD;                 // [i][s] 128 x BPAD
    float* w0s = (float*)(H1s + 128*BPAD);                 // 256
    float* b0s = w0s + 256;                                // 128
    float* b1s = b0s + 128;                                // 128
    float* w2s = b1s + 128;                                // 128

    int t = threadIdx.x;
    int lane = t & 31, warp = t >> 5;
    int j = blockIdx.x, bg = blockIdx.y;

    // stage pre-converted W1^T (32KB) via uint4
    {
        const uint4* src = (const uint4*)w1t;
        for (int idx = t; idx < 2048; idx += 128) {
            int n = idx >> 4, c16 = idx & 15;
            *(uint4*)(W1Ts + n*BPAD + c16*8) = src[idx];
        }
    }
    for (int idx = t; idx < 256; idx += 128) w0s[idx] = w0[idx];
    b0s[t] = b0[t];
    b1s[t] = b1[t];
    w2s[t] = w2[t];
    float kvx = grid[bg*128 + j*2], kvy = grid[bg*128 + j*2 + 1];
    float b2v = b2[0];
    __syncthreads();

    uint32_t h1base = (uint32_t)__cvta_generic_to_shared(H1s);
    uint32_t w1base = (uint32_t)__cvta_generic_to_shared(W1Ts);
    size_t bgbase = (size_t)bg * (Pp*P2);
    int m0 = 32*warp;

    for (int it = 0; it < 8; it++) {
        int i0 = it*128;

        // build H1 row t
        {
            int i = i0 + t;
            float qx = 2.f * (float)(i & 31) * (1.f/31.f) - 1.f;
            float qy = 2.f * (float)(i >> 5) * (1.f/31.f) - 1.f;
            float px = qx - kvx, py = qy - kvy;
            float fx = copysignf(log1pf(fabsf(px)), px);
            float fy = copysignf(log1pf(fabsf(py)), py);
            __nv_bfloat162* rowp = (__nv_bfloat162*)(H1s + t*BPAD);
            #pragma unroll 8
            for (int s = 0; s < 128; s += 2) {
                float h0 = fmaxf(fmaf(fy, w0s[128+s],   fmaf(fx, w0s[s],   b0s[s])),   0.f);
                float h1v= fmaxf(fmaf(fy, w0s[128+s+1], fmaf(fx, w0s[s+1], b0s[s+1])), 0.f);
                rowp[s>>1] = __floats2bfloat162_rn(h0, h1v);
            }
        }
        __syncthreads();

        float rs[4] = {0.f, 0.f, 0.f, 0.f};
        int arow = (lane & 7) + ((lane >> 3) & 1) * 8;
        int acolq = (lane >> 4) * 8;
        int bn_off = (lane >> 4) * 8 + (lane & 7);
        int bcol = ((lane >> 3) & 1) * 8;

        for (int nh = 0; nh < 2; nh++) {
            float c[2][8][4] = {};
            #pragma unroll
            for (int k8 = 0; k8 < 8; k8++) {
                int k0 = k8 * 16;
                uint32_t A[2][4];
                #pragma unroll
                for (int mt = 0; mt < 2; mt++) {
                    int row = m0 + mt*16 + arow;
                    uint32_t addr = h1base + (uint32_t)(row*BPAD + k0 + acolq) * 2u;
                    ldsm4(addr, A[mt][0], A[mt][1], A[mt][2], A[mt][3]);
                }
                uint32_t Bf[4][4];
                #pragma unroll
                for (int np = 0; np < 4; np++) {
                    int n = nh*64 + np*16 + bn_off;
                    uint32_t addr = w1base + (uint32_t)(n*BPAD + k0 + bcol) * 2u;
                    ldsm4(addr, Bf[np][0], Bf[np][1], Bf[np][2], Bf[np][3]);
                }
                #pragma unroll
                for (int nt = 0; nt < 8; nt++) {
                    uint32_t bb0 = Bf[nt>>1][(nt&1)*2], bb1 = Bf[nt>>1][(nt&1)*2+1];
                    mma_bf16(c[0][nt], A[0], bb0, bb1);
                    mma_bf16(c[1][nt], A[1], bb0, bb1);
                }
            }
            #pragma unroll
            for (int nt = 0; nt < 8; nt++) {
                int n = nh*64 + nt*8 + 2*(lane & 3);
                float b1a = b1s[n], b1b = b1s[n+1];
                float w2a = w2s[n], w2b = w2s[n+1];
                #pragma unroll
                for (int mt = 0; mt < 2; mt++) {
                    rs[mt*2+0] += fmaxf(c[mt][nt][0]+b1a, 0.f)*w2a + fmaxf(c[mt][nt][1]+b1b, 0.f)*w2b;
                    rs[mt*2+1] += fmaxf(c[mt][nt][2]+b1a, 0.f)*w2a + fmaxf(c[mt][nt][3]+b1b, 0.f)*w2b;
                }
            }
        }
        #pragma unroll
        for (int k = 0; k < 4; k++) {
            rs[k] += __shfl_xor_sync(0xffffffffu, rs[k], 1);
            rs[k] += __shfl_xor_sync(0xffffffffu, rs[k], 2);
        }
        if ((lane & 3) == 0) {
            int gid = lane >> 2;
            #pragma unroll
            for (int mt = 0; mt < 2; mt++) {
                int i1 = i0 + m0 + mt*16 + gid;
                bias[bgbase + (size_t)i1*64 + j]     = rs[mt*2+0] + b2v;
                bias[bgbase + (size_t)(i1+8)*64 + j] = rs[mt*2+1] + b2v;
            }
        }
        __syncthreads();
    }
}

// ======================= fused attention =======================
// grid (8 i-tiles, 16 bh), 128 threads. k/v/bias staged in smem; one thread per i.
__global__ __launch_bounds__(128, 1)
void attn_fused_kernel(const float* __restrict__ q, const float* __restrict__ k,
                       const float* __restrict__ v, const float* __restrict__ bias,
                       float* __restrict__ out) {
    extern __shared__ float sm[];
    float* att = sm;               // [128][65]
    float* ks  = att + 128*65;     // [64][64]
    float* vs  = ks + 64*64;       // [64][64]

    int t = threadIdx.x;
    int i0 = blockIdx.x * 128, bh = blockIdx.y;
    int b = bh >> 3, h = bh & 7;

    const float* kb = k + ((size_t)b*Cch + h*64)*P2;
    const float* vb = v + ((size_t)b*Cch + h*64)*P2;
    const float* qb = q + ((size_t)b*Cch + h*64)*Pp;
    const float* bb = bias + (size_t)bh*(Pp*P2);
    float* ob = out + ((size_t)b*Cch + h*64)*Pp;

    for (int idx = t; idx < 4096; idx += 128) {
        ks[idx] = kb[idx];
        vs[idx] = vb[idx];
    }
    for (int idx = t; idx < 128*64; idx += 128) {
        int i = idx >> 6, jj = idx & 63;
        att[i*65 + jj] = bb[(size_t)(i0+i)*64 + jj];
    }
    float ql[64];
    #pragma unroll
    for (int d = 0; d < 64; d++) ql[d] = qb[d*Pp + i0 + t] * SCALE;
    __syncthreads();

    float* arow = att + t*65;
    float mx = -1e30f;
    #pragma unroll 2
    for (int jj = 0; jj < 64; jj++) {
        float s = arow[jj];
        #pragma unroll
        for (int d = 0; d < 64; d++) s += ql[d] * ks[d*64 + jj];
        arow[jj] = s;
        mx = fmaxf(mx, s);
    }
    float sum = 0.f;
    #pragma unroll 4
    for (int jj = 0; jj < 64; jj++) {
        float e = __expf(arow[jj] - mx);
        arow[jj] = e;
        sum += e;
    }
    float inv = 1.f / sum;

    int i = i0 + t;
    #pragma unroll
    for (int half = 0; half < 2; half++) {
        float o[32];
        #pragma unroll
        for (int d = 0; d < 32; d++) o[d] = 0.f;
        #pragma unroll 2
        for (int jj = 0; jj < 64; jj++) {
            float a = arow[jj];
            #pragma unroll
            for (int d = 0; d < 32; d++) o[d] += a * vs[(half*32 + d)*64 + jj];
        }
        #pragma unroll
        for (int d = 0; d < 32; d++) ob[(size_t)(half*32 + d)*Pp + i] = o[d] * inv;
    }
}

// ======================= tf32 tensor-core GEMM =======================
__device__ __forceinline__ uint32_t f2tf32(float v) {
    uint32_t u;
    asm("cvt.rna.tf32.f32 %0, %1;" : "=r"(u) : "f"(v));
    return u;
}
__device__ __forceinline__ void mma_tf32(float* c, const uint32_t* a, uint32_t b0, uint32_t b1) {
    asm volatile("mma.sync.aligned.m16n8k8.row.col.f32.tf32.tf32.f32 "
                 "{%0,%1,%2,%3}, {%4,%5,%6,%7}, {%8,%9}, {%0,%1,%2,%3};"
                 : "+f"(c[0]), "+f"(c[1]), "+f"(c[2]), "+f"(c[3])
                 : "r"(a[0]), "r"(a[1]), "r"(a[2]), "r"(a[3]), "r"(b0), "r"(b1));
}

__global__ void gemm_tf32_kernel(const float* __restrict__ A, const float* __restrict__ W,
                                 const float* __restrict__ bias, const float* __restrict__ res,
                                 float* __restrict__ out, int Cin, int act) {
    const int P = 1024;
    int b = blockIdx.z;
    int O = gridDim.y * 128;
    int p0 = blockIdx.x * 128, o0 = blockIdx.y * 128;
    const float* Ab = A + (size_t)b*Cin*P;

    __shared__ uint32_t Wt[128][36];   // [o][c] tf32
    __shared__ uint32_t Xt[32][136];   // [c][p] tf32

    int t = threadIdx.x;
    int lane = t & 31, warp = t >> 5;
    int gid = lane >> 2, ctid = lane & 3;
    int m0w = (warp >> 1) * 32, n0w = (warp & 1) * 64;

    float c[2][8][4] = {};

    for (int cc = 0; cc < Cin; cc += 32) {
        __syncthreads();
        #pragma unroll 4
        for (int idx = t; idx < 4096; idx += 256) {
            int r = idx >> 5, q = idx & 31;
            Wt[r][q] = f2tf32(W[(size_t)(o0 + r)*Cin + cc + q]);
        }
        #pragma unroll 4
        for (int idx = t; idx < 4096; idx += 256) {
            int r = idx >> 7, q = idx & 127;
            Xt[r][q] = f2tf32(Ab[(size_t)(cc + r)*P + p0 + q]);
        }
        __syncthreads();
        #pragma unroll
        for (int k0 = 0; k0 < 32; k0 += 8) {
            uint32_t a[2][4];
            #pragma unroll
            for (int mt = 0; mt < 2; mt++) {
                int row = m0w + mt*16;
                a[mt][0] = Wt[row + gid    ][k0 + ctid];
                a[mt][1] = Wt[row + 8 + gid][k0 + ctid];
                a[mt][2] = Wt[row + gid    ][k0 + ctid + 4];
                a[mt][3] = Wt[row + 8 + gid][k0 + ctid + 4];
            }
            #pragma unroll
            for (int nt = 0; nt < 8; nt++) {
                int n = n0w + nt*8 + gid;
                uint32_t b0v = Xt[k0 + ctid    ][n];
                uint32_t b1v = Xt[k0 + ctid + 4][n];
                mma_tf32(c[0][nt], a[0], b0v, b1v);
                mma_tf32(c[1][nt], a[1], b0v, b1v);
            }
        }
    }

    float* ob = out + (size_t)b*O*P;
    const float* rb = res ? res + (size_t)b*O*P : nullptr;
    #pragma unroll
    for (int mt = 0; mt < 2; mt++) {
        #pragma unroll
        for (int half = 0; half < 2; half++) {
            int o = o0 + m0w + mt*16 + gid + half*8;
            float bv = bias[o];
            #pragma unroll
            for (int nt = 0; nt < 8; nt++) {
                int p = p0 + n0w + nt*8 + 2*ctid;
                float v0 = c[mt][nt][half*2+0] + bv;
                float v1 = c[mt][nt][half*2+1] + bv;
                if (act == 1) {
                    v0 = 0.5f * v0 * (1.f + erff(v0 * 0.70710678118654752f));
                    v1 = 0.5f * v1 * (1.f + erff(v1 * 0.70710678118654752f));
                }
                if (rb) {
                    const float2 rv = *(const float2*)&rb[(size_t)o*P + p];
                    v0 += rv.x; v1 += rv.y;
                }
                float2 st; st.x = v0; st.y = v1;
                *(float2*)&ob[(size_t)o*P + p] = st;
            }
        }
    }
}

// ---------------- launch ----------------
extern "C" void kernel_launch(void* const* d_in, const int* in_sizes, int n_in,
                              void* d_out, int out_size) {
    const float* x        = (const float*)d_in[0];
    const float* n1_g     = (const float*)d_in[1];
    const float* n1_b     = (const float*)d_in[2];
    const float* n2_g     = (const float*)d_in[3];
    const float* n2_b     = (const float*)d_in[4];
    const float* q_w      = (const float*)d_in[5];
    const float* k_w      = (const float*)d_in[6];
    const float* v_w      = (const float*)d_in[7];
    const float* off_dw_w = (const float*)d_in[8];
    const float* off_dw_b = (const float*)d_in[9];
    const float* off_pw_w = (const float*)d_in[10];
    const float* cpb_w0   = (const float*)d_in[11];
    const float* cpb_b0   = (const float*)d_in[12];
    const float* cpb_w1   = (const float*)d_in[13];
    const float* cpb_b1   = (const float*)d_in[14];
    const float* cpb_w2   = (const float*)d_in[15];
    const float* cpb_b2   = (const float*)d_in[16];
    const float* out_w    = (const float*)d_in[17];
    const float* out_b    = (const float*)d_in[18];
    const float* mlp_w1   = (const float*)d_in[19];
    const float* mlp_b1   = (const float*)d_in[20];
    const float* mlp_w2   = (const float*)d_in[21];
    const float* mlp_b2   = (const float*)d_in[22];
    float* out = (float*)d_out;

    float *p_xn, *p_q, *p_grid, *p_kv, *p_k, *p_v, *p_bias, *p_ao, *p_x1, *p_h, *p_m1;
    __nv_bfloat16* p_w1t;
    cudaGetSymbolAddress((void**)&p_xn,   g_xn);
    cudaGetSymbolAddress((void**)&p_q,    g_q);
    cudaGetSymbolAddress((void**)&p_grid, g_grid);
    cudaGetSymbolAddress((void**)&p_kv,   g_kv);
    cudaGetSymbolAddress((void**)&p_k,    g_k);
    cudaGetSymbolAddress((void**)&p_v,    g_v);
    cudaGetSymbolAddress((void**)&p_bias, g_bias);
    cudaGetSymbolAddress((void**)&p_ao,   g_ao);
    cudaGetSymbolAddress((void**)&p_x1,   g_x1);
    cudaGetSymbolAddress((void**)&p_h,    g_h);
    cudaGetSymbolAddress((void**)&p_m1,   g_m1);
    cudaGetSymbolAddress((void**)&p_w1t,  g_w1t);

    // one-time W1 convert (cheap, no deps)
    w1cvt_kernel<<<64, 256>>>(cpb_w1);
    // batchnorm1
    bn_kernel<<<512, 256>>>(x, n1_g, n1_b, p_xn);
    // q grouped conv
    gconv_kernel<<<dim3(16, 16), 256>>>(p_xn, q_w, p_q, Pp);
    // fused dwconv+gelu -> offsets -> grid -> bilinear sample
    offs_fused_kernel<<<16, 256>>>(p_q, off_dw_w, off_dw_b, off_pw_w, p_xn, p_grid, p_kv);
    // k + v grouped convs (fused)
    gconv_kv_kernel<<<16, 256>>>(p_kv, k_w, v_w, p_k, p_v);
    // CPB bias MLP (bf16 tensor cores)
    {
        int smem = 2*128*BPAD*2 + (256 + 128 + 128 + 128)*4;
        cudaFuncSetAttribute(bias_mma_kernel, cudaFuncAttributeMaxDynamicSharedMemorySize, smem);
        bias_mma_kernel<<<dim3(64, 16), 128, smem>>>(p_grid, cpb_w0, cpb_b0, p_w1t, cpb_b1,
                                                     cpb_w2, cpb_b2, p_bias);
    }
    // fused attention
    {
        int smem = (128*65 + 64*64 + 64*64) * 4;
        cudaFuncSetAttribute(attn_fused_kernel, cudaFuncAttributeMaxDynamicSharedMemorySize, smem);
        attn_fused_kernel<<<dim3(8, 16), 128, smem>>>(p_q, p_k, p_v, p_bias, p_ao);
    }
    // out projection + residual (tf32)
    gemm_tf32_kernel<<<dim3(8, 4, 2), 256>>>(p_ao, out_w, out_b, x, p_x1, 512, 0);
    // batchnorm2
    bn_kernel<<<512, 256>>>(p_x1, n2_g, n2_b, p_h);
    // mlp1 + gelu (tf32)
    gemm_tf32_kernel<<<dim3(8, 16, 2), 256>>>(p_h, mlp_w1, mlp_b1, nullptr, p_m1, 512, 1);
    // mlp2 + residual (tf32)
    gemm_tf32_kernel<<<dim3(8, 4, 2), 256>>>(p_m1, mlp_w2, mlp_b2, p_x1, out, 2048, 0);
}

// round 7
// speedup vs baseline: 5.4155x; 1.8032x over previous
#include <cuda_runtime.h>
#include <cuda_bf16.h>
#include <stdint.h>
#include <math.h>

// Problem constants
#define Bsz 2
#define Cch 512
#define Gg  8
#define Cg  64
#define Pp  1024          // H*W
#define P2  64            // H2*W2
#define SCALE 0.125f

// ---------------- scratch (static device globals; no allocation) ----------------
__device__ float g_xn  [Bsz*Cch*Pp];
__device__ float g_q   [Bsz*Cch*Pp];
__device__ float g_off1[16*Cg*P2];
__device__ float g_grid[16*P2*2];
__device__ float g_k   [Bsz*Cch*P2];
__device__ float g_v   [Bsz*Cch*P2];
__device__ float g_bias[16*Pp*P2];
__device__ float g_ao  [Bsz*Cch*Pp];
__device__ float g_x1  [Bsz*Cch*Pp];
__device__ float g_m1  [Bsz*2048*Pp];
__device__ float g_bnsc[Cch];
__device__ float g_bnsh[Cch];
__device__ __nv_bfloat16 g_w1t[128*128];   // W1^T bf16, [n][s]

// ---------------- batchnorm (full normalize) ----------------
__global__ void bn_kernel(const float* __restrict__ x, const float* __restrict__ g,
                          const float* __restrict__ b, float* __restrict__ y) {
    int c = blockIdx.x, t = threadIdx.x;
    __shared__ float ssum[256], ssq[256];
    float s = 0.f, q = 0.f;
    for (int idx = t; idx < 2048; idx += 256) {
        int bb = idx >> 10, p = idx & 1023;
        float v = x[bb*(Cch*Pp) + c*Pp + p];
        s += v; q += v*v;
    }
    ssum[t] = s; ssq[t] = q; __syncthreads();
    for (int o = 128; o > 0; o >>= 1) {
        if (t < o) { ssum[t] += ssum[t+o]; ssq[t] += ssq[t+o]; }
        __syncthreads();
    }
    float m  = ssum[0] * (1.f/2048.f);
    float var = ssq[0] * (1.f/2048.f) - m*m;
    float rs = rsqrtf(var + 1e-5f);
    float gg = g[c] * rs;
    float bb2 = b[c] - m * gg;
    for (int idx = t; idx < 2048; idx += 256) {
        int bb = idx >> 10, p = idx & 1023;
        y[bb*(Cch*Pp) + c*Pp + p] = x[bb*(Cch*Pp) + c*Pp + p] * gg + bb2;
    }
}

// ---------------- batchnorm stats only (scale/shift per channel) ----------------
__global__ void bn_stats_kernel(const float* __restrict__ x, const float* __restrict__ g,
                                const float* __restrict__ b, float* __restrict__ sc,
                                float* __restrict__ sh) {
    int c = blockIdx.x, t = threadIdx.x;
    __shared__ float ssum[256], ssq[256];
    float s = 0.f, q = 0.f;
    for (int idx = t; idx < 2048; idx += 256) {
        int bb = idx >> 10, p = idx & 1023;
        float v = x[bb*(Cch*Pp) + c*Pp + p];
        s += v; q += v*v;
    }
    ssum[t] = s; ssq[t] = q; __syncthreads();
    for (int o = 128; o > 0; o >>= 1) {
        if (t < o) { ssum[t] += ssum[t+o]; ssq[t] += ssq[t+o]; }
        __syncthreads();
    }
    if (t == 0) {
        float m  = ssum[0] * (1.f/2048.f);
        float var = ssq[0] * (1.f/2048.f) - m*m;
        float rs = rsqrtf(var + 1e-5f);
        float gg = g[c] * rs;
        sc[c] = gg;
        sh[c] = b[c] - m * gg;
    }
}

// ---------------- grouped 1x1 conv (q) ----------------
__global__ void gconv_kernel(const float* __restrict__ in, const float* __restrict__ w,
                             float* __restrict__ out, int P) {
    int bg = blockIdx.x, pt = blockIdx.y;
    int grp = bg & 7;
    const float* A  = in + (size_t)bg*Cg*P + pt*64;
    const float* Wg = w + grp*4096;
    float* O        = out + (size_t)bg*Cg*P + pt*64;
    __shared__ float As[64][64];
    __shared__ float Ws[64][64];
    int t = threadIdx.x;
    for (int idx = t; idx < 4096; idx += 256) {
        int r = idx >> 6, q = idx & 63;
        As[r][q] = A[r*P + q];
        ((float*)Ws)[idx] = Wg[idx];
    }
    __syncthreads();
    int tp = (t & 15) * 4, to = (t >> 4) * 4;
    float acc[4][4] = {};
    #pragma unroll
    for (int c = 0; c < 64; c += 4) {
        float4 a[4], wv[4];
        #pragma unroll
        for (int u = 0; u < 4; u++) a[u] = *(const float4*)&As[c+u][tp];
        #pragma unroll
        for (int oi = 0; oi < 4; oi++) wv[oi] = *(const float4*)&Ws[to+oi][c];
        #pragma unroll
        for (int oi = 0; oi < 4; oi++) {
            float wf[4] = {wv[oi].x, wv[oi].y, wv[oi].z, wv[oi].w};
            #pragma unroll
            for (int u = 0; u < 4; u++) {
                acc[oi][0] += wf[u]*a[u].x; acc[oi][1] += wf[u]*a[u].y;
                acc[oi][2] += wf[u]*a[u].z; acc[oi][3] += wf[u]*a[u].w;
            }
        }
    }
    #pragma unroll
    for (int oi = 0; oi < 4; oi++)
        #pragma unroll
        for (int pj = 0; pj < 4; pj++)
            O[(to+oi)*P + tp+pj] = acc[oi][pj];
}

// ---------------- depthwise 6x6 stride-4 pad-1 conv + bias + exact gelu (wide) ----------------
__global__ void dwconv_kernel(const float* __restrict__ q, const float* __restrict__ dw,
                              const float* __restrict__ db, float* __restrict__ out) {
    int idx = blockIdx.x*blockDim.x + threadIdx.x;
    if (idx >= 16*Cg*P2) return;
    int p = idx & 63, c = (idx >> 6) & 63, bg = idx >> 12;
    int oy = p >> 3, ox = p & 7;
    float acc = db[c];
    const float* ip = q + (size_t)bg*Cg*Pp + c*Pp;
    const float* wp = dw + c*36;
    #pragma unroll
    for (int ky = 0; ky < 6; ky++) {
        int iy = oy*4 - 1 + ky;
        if (iy < 0 || iy >= 32) continue;
        #pragma unroll
        for (int kx = 0; kx < 6; kx++) {
            int ix = ox*4 - 1 + kx;
            if (ix < 0 || ix >= 32) continue;
            acc += ip[iy*32 + ix] * wp[ky*6 + kx];
        }
    }
    out[idx] = 0.5f * acc * (1.f + erff(acc * 0.70710678118654752f));
}

// ---------------- pointwise 64->2, tanh*4, build grid (256 thr, split-c reduce) ----------------
__global__ void offset_kernel(const float* __restrict__ off1, const float* __restrict__ pw,
                              float* __restrict__ grid) {
    __shared__ float part[2][4][64];
    int bg = blockIdx.x, t = threadIdx.x;
    int qd = t >> 6, p = t & 63;
    const float* base = off1 + bg*(Cg*P2);
    float s0 = 0.f, s1 = 0.f;
    #pragma unroll
    for (int cc = 0; cc < 16; cc++) {
        int c = qd*16 + cc;
        float v = base[c*64 + p];
        s0 = fmaf(v, pw[c], s0);
        s1 = fmaf(v, pw[64 + c], s1);
    }
    part[0][qd][p] = s0;
    part[1][qd][p] = s1;
    __syncthreads();
    if (t < 64) {
        float t0 = part[0][0][t] + part[0][1][t] + part[0][2][t] + part[0][3][t];
        float t1 = part[1][0][t] + part[1][1][t] + part[1][2][t] + part[1][3][t];
        float ox = tanhf(t0) * 4.f, oy = tanhf(t1) * 4.f;
        float gx = (float)(t & 7), gy = (float)(t >> 3);
        grid[bg*128 + t*2]   = 2.f * (gx + ox) * (1.f/7.f) - 1.f;
        grid[bg*128 + t*2+1] = 2.f * (gy + oy) * (1.f/7.f) - 1.f;
    }
}

// ---------------- grouped conv k,v with INLINE bilinear sampling of A ----------------
__global__ void gconv_kv_kernel(const float* __restrict__ xn, const float* __restrict__ grid,
                                const float* __restrict__ kw, const float* __restrict__ vw,
                                float* __restrict__ kout, float* __restrict__ vout) {
    const int P = P2;
    int bg = blockIdx.x;
    int grp = bg & 7;
    __shared__ float sgrid[128];
    __shared__ float As[64][64];
    __shared__ float Wk[64][64];
    __shared__ float Wv[64][64];
    int t = threadIdx.x;
    if (t < 128) sgrid[t] = grid[bg*128 + t];
    for (int idx = t; idx < 4096; idx += 256) {
        ((float*)Wk)[idx] = kw[grp*4096 + idx];
        ((float*)Wv)[idx] = vw[grp*4096 + idx];
    }
    __syncthreads();
    // sample A = kv[c][p] directly from xn
    for (int idx = t; idx < 4096; idx += 256) {
        int p = idx & 63, c = idx >> 6;
        float vx = sgrid[p*2], vy = sgrid[p*2+1];
        float x = ((vx + 1.f) * 32.f - 1.f) * 0.5f;
        float y = ((vy + 1.f) * 32.f - 1.f) * 0.5f;
        float x0f = floorf(x), y0f = floorf(y);
        int x0 = (int)x0f, y0 = (int)y0f;
        float wx = x - x0f, wy = y - y0f;
        const float* im = xn + (size_t)bg*Cg*Pp + c*Pp;
        float v00 = (x0   >= 0 && x0   < 32 && y0   >= 0 && y0   < 32) ? im[y0*32 + x0]       : 0.f;
        float v10 = (x0+1 >= 0 && x0+1 < 32 && y0   >= 0 && y0   < 32) ? im[y0*32 + x0+1]     : 0.f;
        float v01 = (x0   >= 0 && x0   < 32 && y0+1 >= 0 && y0+1 < 32) ? im[(y0+1)*32 + x0]   : 0.f;
        float v11 = (x0+1 >= 0 && x0+1 < 32 && y0+1 >= 0 && y0+1 < 32) ? im[(y0+1)*32 + x0+1] : 0.f;
        As[c][p] = v00*(1.f-wx)*(1.f-wy) + v10*wx*(1.f-wy) + v01*(1.f-wx)*wy + v11*wx*wy;
    }
    __syncthreads();
    int tp = (t & 15) * 4, to = (t >> 4) * 4;
    float ak[4][4] = {}, av[4][4] = {};
    #pragma unroll
    for (int c = 0; c < 64; c += 4) {
        float4 a[4], wk[4], wv[4];
        #pragma unroll
        for (int u = 0; u < 4; u++) a[u] = *(const float4*)&As[c+u][tp];
        #pragma unroll
        for (int oi = 0; oi < 4; oi++) {
            wk[oi] = *(const float4*)&Wk[to+oi][c];
            wv[oi] = *(const float4*)&Wv[to+oi][c];
        }
        #pragma unroll
        for (int oi = 0; oi < 4; oi++) {
            float kf[4] = {wk[oi].x, wk[oi].y, wk[oi].z, wk[oi].w};
            float vf[4] = {wv[oi].x, wv[oi].y, wv[oi].z, wv[oi].w};
            #pragma unroll
            for (int u = 0; u < 4; u++) {
                ak[oi][0] += kf[u]*a[u].x; ak[oi][1] += kf[u]*a[u].y;
                ak[oi][2] += kf[u]*a[u].z; ak[oi][3] += kf[u]*a[u].w;
                av[oi][0] += vf[u]*a[u].x; av[oi][1] += vf[u]*a[u].y;
                av[oi][2] += vf[u]*a[u].z; av[oi][3] += vf[u]*a[u].w;
            }
        }
    }
    float* KO = kout + (size_t)bg*Cg*P;
    float* VO = vout + (size_t)bg*Cg*P;
    #pragma unroll
    for (int oi = 0; oi < 4; oi++)
        #pragma unroll
        for (int pj = 0; pj < 4; pj++) {
            KO[(to+oi)*P + tp+pj] = ak[oi][pj];
            VO[(to+oi)*P + tp+pj] = av[oi][pj];
        }
}

// ---------------- one-time W1 -> bf16 transpose/convert ----------------
__global__ void w1cvt_kernel(const float* __restrict__ w1) {
    int idx = blockIdx.x*256 + threadIdx.x;  // 16384
    int s = idx >> 7, n = idx & 127;
    g_w1t[n*128 + s] = __float2bfloat16(w1[idx]);
}

// ======================= CPB bias MLP — bf16 tensor cores =======================
#define BPAD 136   // bf16 row stride (halfs)

__device__ __forceinline__ void ldsm4(uint32_t addr, uint32_t& r0, uint32_t& r1,
                                      uint32_t& r2, uint32_t& r3) {
    asm volatile("ldmatrix.sync.aligned.m8n8.x4.shared.b16 {%0,%1,%2,%3}, [%4];"
                 : "=r"(r0), "=r"(r1), "=r"(r2), "=r"(r3) : "r"(addr));
}
__device__ __forceinline__ void mma_bf16(float* c, const uint32_t* a, uint32_t b0, uint32_t b1) {
    asm volatile("mma.sync.aligned.m16n8k16.row.col.f32.bf16.bf16.f32 "
                 "{%0,%1,%2,%3}, {%4,%5,%6,%7}, {%8,%9}, {%0,%1,%2,%3};"
                 : "+f"(c[0]), "+f"(c[1]), "+f"(c[2]), "+f"(c[3])
                 : "r"(a[0]), "r"(a[1]), "r"(a[2]), "r"(a[3]), "r"(b0), "r"(b1));
}

__global__ __launch_bounds__(128, 3)
void bias_mma_kernel(const float* __restrict__ grid,
                     const float* __restrict__ w0, const float* __restrict__ b0,
                     const __nv_bfloat16* __restrict__ w1t,
                     const float* __restrict__ b1,
                     const float* __restrict__ w2, const float* __restrict__ b2,
                     float* __restrict__ bias) {
    extern __shared__ unsigned char smraw[];
    __nv_bfloat16* W1Ts = (__nv_bfloat16*)smraw;           // [n][s] 128 x BPAD
    __nv_bfloat16* H1s  = W1Ts + 128*BPAD;                 // [i][s] 128 x BPAD
    float* w0s = (float*)(H1s + 128*BPAD);                 // 256
    float* b0s = w0s + 256;                                // 128
    float* b1s = b0s + 128;                                // 128
    float* w2s = b1s + 128;                                // 128

    int t = threadIdx.x;
    int lane = t & 31, warp = t >> 5;
    int j = blockIdx.x, bg = blockIdx.y;

    {
        const uint4* src = (const uint4*)w1t;
        for (int idx = t; idx < 2048; idx += 128) {
            int n = idx >> 4, c16 = idx & 15;
            *(uint4*)(W1Ts + n*BPAD + c16*8) = src[idx];
        }
    }
    for (int idx = t; idx < 256; idx += 128) w0s[idx] = w0[idx];
    b0s[t] = b0[t];
    b1s[t] = b1[t];
    w2s[t] = w2[t];
    float kvx = grid[bg*128 + j*2], kvy = grid[bg*128 + j*2 + 1];
    float b2v = b2[0];
    __syncthreads();

    uint32_t h1base = (uint32_t)__cvta_generic_to_shared(H1s);
    uint32_t w1base = (uint32_t)__cvta_generic_to_shared(W1Ts);
    size_t bgbase = (size_t)bg * (Pp*P2);
    int m0 = 32*warp;

    for (int it = 0; it < 8; it++) {
        int i0 = it*128;
        {
            int i = i0 + t;
            float qx = 2.f * (float)(i & 31) * (1.f/31.f) - 1.f;
            float qy = 2.f * (float)(i >> 5) * (1.f/31.f) - 1.f;
            float px = qx - kvx, py = qy - kvy;
            float fx = copysignf(log1pf(fabsf(px)), px);
            float fy = copysignf(log1pf(fabsf(py)), py);
            __nv_bfloat162* rowp = (__nv_bfloat162*)(H1s + t*BPAD);
            #pragma unroll 8
            for (int s = 0; s < 128; s += 2) {
                float h0 = fmaxf(fmaf(fy, w0s[128+s],   fmaf(fx, w0s[s],   b0s[s])),   0.f);
                float h1v= fmaxf(fmaf(fy, w0s[128+s+1], fmaf(fx, w0s[s+1], b0s[s+1])), 0.f);
                rowp[s>>1] = __floats2bfloat162_rn(h0, h1v);
            }
        }
        __syncthreads();

        float rs[4] = {0.f, 0.f, 0.f, 0.f};
        int arow = (lane & 7) + ((lane >> 3) & 1) * 8;
        int acolq = (lane >> 4) * 8;
        int bn_off = (lane >> 4) * 8 + (lane & 7);
        int bcol = ((lane >> 3) & 1) * 8;

        for (int nh = 0; nh < 2; nh++) {
            float c[2][8][4] = {};
            #pragma unroll
            for (int k8 = 0; k8 < 8; k8++) {
                int k0 = k8 * 16;
                uint32_t A[2][4];
                #pragma unroll
                for (int mt = 0; mt < 2; mt++) {
                    int row = m0 + mt*16 + arow;
                    uint32_t addr = h1base + (uint32_t)(row*BPAD + k0 + acolq) * 2u;
                    ldsm4(addr, A[mt][0], A[mt][1], A[mt][2], A[mt][3]);
                }
                uint32_t Bf[4][4];
                #pragma unroll
                for (int np = 0; np < 4; np++) {
                    int n = nh*64 + np*16 + bn_off;
                    uint32_t addr = w1base + (uint32_t)(n*BPAD + k0 + bcol) * 2u;
                    ldsm4(addr, Bf[np][0], Bf[np][1], Bf[np][2], Bf[np][3]);
                }
                #pragma unroll
                for (int nt = 0; nt < 8; nt++) {
                    uint32_t bb0 = Bf[nt>>1][(nt&1)*2], bb1 = Bf[nt>>1][(nt&1)*2+1];
                    mma_bf16(c[0][nt], A[0], bb0, bb1);
                    mma_bf16(c[1][nt], A[1], bb0, bb1);
                }
            }
            #pragma unroll
            for (int nt = 0; nt < 8; nt++) {
                int n = nh*64 + nt*8 + 2*(lane & 3);
                float b1a = b1s[n], b1b = b1s[n+1];
                float w2a = w2s[n], w2b = w2s[n+1];
                #pragma unroll
                for (int mt = 0; mt < 2; mt++) {
                    rs[mt*2+0] += fmaxf(c[mt][nt][0]+b1a, 0.f)*w2a + fmaxf(c[mt][nt][1]+b1b, 0.f)*w2b;
                    rs[mt*2+1] += fmaxf(c[mt][nt][2]+b1a, 0.f)*w2a + fmaxf(c[mt][nt][3]+b1b, 0.f)*w2b;
                }
            }
        }
        #pragma unroll
        for (int k = 0; k < 4; k++) {
            rs[k] += __shfl_xor_sync(0xffffffffu, rs[k], 1);
            rs[k] += __shfl_xor_sync(0xffffffffu, rs[k], 2);
        }
        if ((lane & 3) == 0) {
            int gid = lane >> 2;
            #pragma unroll
            for (int mt = 0; mt < 2; mt++) {
                int i1 = i0 + m0 + mt*16 + gid;
                bias[bgbase + (size_t)i1*64 + j]     = rs[mt*2+0] + b2v;
                bias[bgbase + (size_t)(i1+8)*64 + j] = rs[mt*2+1] + b2v;
            }
        }
        __syncthreads();
    }
}

// ======================= fused attention =======================
__global__ __launch_bounds__(128, 1)
void attn_fused_kernel(const float* __restrict__ q, const float* __restrict__ k,
                       const float* __restrict__ v, const float* __restrict__ bias,
                       float* __restrict__ out) {
    extern __shared__ float sm[];
    float* att = sm;               // [128][65]
    float* ks  = att + 128*65;     // [64][64]
    float* vs  = ks + 64*64;       // [64][64]

    int t = threadIdx.x;
    int i0 = blockIdx.x * 128, bh = blockIdx.y;
    int b = bh >> 3, h = bh & 7;

    const float* kb = k + ((size_t)b*Cch + h*64)*P2;
    const float* vb = v + ((size_t)b*Cch + h*64)*P2;
    const float* qb = q + ((size_t)b*Cch + h*64)*Pp;
    const float* bb = bias + (size_t)bh*(Pp*P2);
    float* ob = out + ((size_t)b*Cch + h*64)*Pp;

    for (int idx = t; idx < 4096; idx += 128) {
        ks[idx] = kb[idx];
        vs[idx] = vb[idx];
    }
    for (int idx = t; idx < 128*64; idx += 128) {
        int i = idx >> 6, jj = idx & 63;
        att[i*65 + jj] = bb[(size_t)(i0+i)*64 + jj];
    }
    float ql[64];
    #pragma unroll
    for (int d = 0; d < 64; d++) ql[d] = qb[d*Pp + i0 + t] * SCALE;
    __syncthreads();

    float* arow = att + t*65;
    float mx = -1e30f;
    #pragma unroll 2
    for (int jj = 0; jj < 64; jj++) {
        float s = arow[jj];
        #pragma unroll
        for (int d = 0; d < 64; d++) s += ql[d] * ks[d*64 + jj];
        arow[jj] = s;
        mx = fmaxf(mx, s);
    }
    float sum = 0.f;
    #pragma unroll 4
    for (int jj = 0; jj < 64; jj++) {
        float e = __expf(arow[jj] - mx);
        arow[jj] = e;
        sum += e;
    }
    float inv = 1.f / sum;

    int i = i0 + t;
    #pragma unroll
    for (int half = 0; half < 2; half++) {
        float o[32];
        #pragma unroll
        for (int d = 0; d < 32; d++) o[d] = 0.f;
        #pragma unroll 2
        for (int jj = 0; jj < 64; jj++) {
            float a = arow[jj];
            #pragma unroll
            for (int d = 0; d < 32; d++) o[d] += a * vs[(half*32 + d)*64 + jj];
        }
        #pragma unroll
        for (int d = 0; d < 32; d++) ob[(size_t)(half*32 + d)*Pp + i] = o[d] * inv;
    }
}

// ======================= tf32 tensor-core GEMM (raw-float smem, cvt at frag load) =======================
__device__ __forceinline__ uint32_t f2tf32(float v) {
    uint32_t u;
    asm("cvt.rna.tf32.f32 %0, %1;" : "=r"(u) : "f"(v));
    return u;
}
__device__ __forceinline__ void mma_tf32(float* c, const uint32_t* a, uint32_t b0, uint32_t b1) {
    asm volatile("mma.sync.aligned.m16n8k8.row.col.f32.tf32.tf32.f32 "
                 "{%0,%1,%2,%3}, {%4,%5,%6,%7}, {%8,%9}, {%0,%1,%2,%3};"
                 : "+f"(c[0]), "+f"(c[1]), "+f"(c[2]), "+f"(c[3])
                 : "r"(a[0]), "r"(a[1]), "r"(a[2]), "r"(a[3]), "r"(b0), "r"(b1));
}

__global__ __launch_bounds__(256)
void gemm_tf32_kernel(const float* __restrict__ A, const float* __restrict__ W,
                      const float* __restrict__ bias, const float* __restrict__ res,
                      float* __restrict__ out, int Cin, int act,
                      const float* __restrict__ bnsc, const float* __restrict__ bnsh) {
    const int P = 1024;
    int b = blockIdx.z;
    int O = gridDim.y * 128;
    int p0 = blockIdx.x * 128, o0 = blockIdx.y * 128;
    const float* Ab = A + (size_t)b*Cin*P;

    __shared__ float Wt[128][36];   // [o][c]
    __shared__ float Xt[32][136];   // [c][p]

    int t = threadIdx.x;
    int lane = t & 31, warp = t >> 5;
    int gid = lane >> 2, ctid = lane & 3;
    int m0w = (warp >> 1) * 32, n0w = (warp & 1) * 64;

    float c[2][8][4] = {};

    for (int cc = 0; cc < Cin; cc += 32) {
        __syncthreads();
        // stage W: 128 rows x 32 cols = 1024 float4
        #pragma unroll
        for (int idx = t; idx < 1024; idx += 256) {
            int r = idx >> 3, q4 = (idx & 7) * 4;
            float4 wv = *(const float4*)&W[(size_t)(o0 + r)*Cin + cc + q4];
            *(float4*)&Wt[r][q4] = wv;
        }
        // stage X: 32 rows x 128 cols = 1024 float4 (+ optional bn affine)
        #pragma unroll
        for (int idx = t; idx < 1024; idx += 256) {
            int r = idx >> 5, q4 = (idx & 31) * 4;
            float4 xv = *(const float4*)&Ab[(size_t)(cc + r)*P + p0 + q4];
            if (bnsc) {
                float s = bnsc[cc + r], h = bnsh[cc + r];
                xv.x = fmaf(xv.x, s, h); xv.y = fmaf(xv.y, s, h);
                xv.z = fmaf(xv.z, s, h); xv.w = fmaf(xv.w, s, h);
            }
            *(float4*)&Xt[r][q4] = xv;
        }
        __syncthreads();
        #pragma unroll
        for (int k0 = 0; k0 < 32; k0 += 8) {
            uint32_t a[2][4];
            #pragma unroll
            for (int mt = 0; mt < 2; mt++) {
                int row = m0w + mt*16;
                a[mt][0] = f2tf32(Wt[row + gid    ][k0 + ctid]);
                a[mt][1] = f2tf32(Wt[row + 8 + gid][k0 + ctid]);
                a[mt][2] = f2tf32(Wt[row + gid    ][k0 + ctid + 4]);
                a[mt][3] = f2tf32(Wt[row + 8 + gid][k0 + ctid + 4]);
            }
            #pragma unroll
            for (int nt = 0; nt < 8; nt++) {
                int n = n0w + nt*8 + gid;
                uint32_t b0v = f2tf32(Xt[k0 + ctid    ][n]);
                uint32_t b1v = f2tf32(Xt[k0 + ctid + 4][n]);
                mma_tf32(c[0][nt], a[0], b0v, b1v);
                mma_tf32(c[1][nt], a[1], b0v, b1v);
            }
        }
    }

    float* ob = out + (size_t)b*O*P;
    const float* rb = res ? res + (size_t)b*O*P : nullptr;
    #pragma unroll
    for (int mt = 0; mt < 2; mt++) {
        #pragma unroll
        for (int half = 0; half < 2; half++) {
            int o = o0 + m0w + mt*16 + gid + half*8;
            float bv = bias[o];
            #pragma unroll
            for (int nt = 0; nt < 8; nt++) {
                int p = p0 + n0w + nt*8 + 2*ctid;
                float v0 = c[mt][nt][half*2+0] + bv;
                float v1 = c[mt][nt][half*2+1] + bv;
                if (act == 1) {
                    v0 = 0.5f * v0 * (1.f + erff(v0 * 0.70710678118654752f));
                    v1 = 0.5f * v1 * (1.f + erff(v1 * 0.70710678118654752f));
                }
                if (rb) {
                    const float2 rv = *(const float2*)&rb[(size_t)o*P + p];
                    v0 += rv.x; v1 += rv.y;
                }
                float2 st; st.x = v0; st.y = v1;
                *(float2*)&ob[(size_t)o*P + p] = st;
            }
        }
    }
}

// ---------------- launch ----------------
extern "C" void kernel_launch(void* const* d_in, const int* in_sizes, int n_in,
                              void* d_out, int out_size) {
    const float* x        = (const float*)d_in[0];
    const float* n1_g     = (const float*)d_in[1];
    const float* n1_b     = (const float*)d_in[2];
    const float* n2_g     = (const float*)d_in[3];
    const float* n2_b     = (const float*)d_in[4];
    const float* q_w      = (const float*)d_in[5];
    const float* k_w      = (const float*)d_in[6];
    const float* v_w      = (const float*)d_in[7];
    const float* off_dw_w = (const float*)d_in[8];
    const float* off_dw_b = (const float*)d_in[9];
    const float* off_pw_w = (const float*)d_in[10];
    const float* cpb_w0   = (const float*)d_in[11];
    const float* cpb_b0   = (const float*)d_in[12];
    const float* cpb_w1   = (const float*)d_in[13];
    const float* cpb_b1   = (const float*)d_in[14];
    const float* cpb_w2   = (const float*)d_in[15];
    const float* cpb_b2   = (const float*)d_in[16];
    const float* out_w    = (const float*)d_in[17];
    const float* out_b    = (const float*)d_in[18];
    const float* mlp_w1   = (const float*)d_in[19];
    const float* mlp_b1   = (const float*)d_in[20];
    const float* mlp_w2   = (const float*)d_in[21];
    const float* mlp_b2   = (const float*)d_in[22];
    float* out = (float*)d_out;

    float *p_xn, *p_q, *p_off1, *p_grid, *p_k, *p_v, *p_bias, *p_ao, *p_x1, *p_m1, *p_sc, *p_sh;
    __nv_bfloat16* p_w1t;
    cudaGetSymbolAddress((void**)&p_xn,   g_xn);
    cudaGetSymbolAddress((void**)&p_q,    g_q);
    cudaGetSymbolAddress((void**)&p_off1, g_off1);
    cudaGetSymbolAddress((void**)&p_grid, g_grid);
    cudaGetSymbolAddress((void**)&p_k,    g_k);
    cudaGetSymbolAddress((void**)&p_v,    g_v);
    cudaGetSymbolAddress((void**)&p_bias, g_bias);
    cudaGetSymbolAddress((void**)&p_ao,   g_ao);
    cudaGetSymbolAddress((void**)&p_x1,   g_x1);
    cudaGetSymbolAddress((void**)&p_m1,   g_m1);
    cudaGetSymbolAddress((void**)&p_sc,   g_bnsc);
    cudaGetSymbolAddress((void**)&p_sh,   g_bnsh);
    cudaGetSymbolAddress((void**)&p_w1t,  g_w1t);

    // one-time W1 convert
    w1cvt_kernel<<<64, 256>>>(cpb_w1);
    // batchnorm1
    bn_kernel<<<512, 256>>>(x, n1_g, n1_b, p_xn);
    // q grouped conv
    gconv_kernel<<<dim3(16, 16), 256>>>(p_xn, q_w, p_q, Pp);
    // depthwise conv + gelu (wide)
    dwconv_kernel<<<256, 256>>>(p_q, off_dw_w, off_dw_b, p_off1);
    // offsets -> grid
    offset_kernel<<<16, 256>>>(p_off1, off_pw_w, p_grid);
    // k + v grouped convs with inline bilinear sampling
    gconv_kv_kernel<<<16, 256>>>(p_xn, p_grid, k_w, v_w, p_k, p_v);
    // CPB bias MLP (bf16 tensor cores)
    {
        int smem = 2*128*BPAD*2 + (256 + 128 + 128 + 128)*4;
        cudaFuncSetAttribute(bias_mma_kernel, cudaFuncAttributeMaxDynamicSharedMemorySize, smem);
        bias_mma_kernel<<<dim3(64, 16), 128, smem>>>(p_grid, cpb_w0, cpb_b0, p_w1t, cpb_b1,
                                                     cpb_w2, cpb_b2, p_bias);
    }
    // fused attention
    {
        int smem = (128*65 + 64*64 + 64*64) * 4;
        cudaFuncSetAttribute(attn_fused_kernel, cudaFuncAttributeMaxDynamicSharedMemorySize, smem);
        attn_fused_kernel<<<dim3(8, 16), 128, smem>>>(p_q, p_k, p_v, p_bias, p_ao);
    }
    // out projection + residual (tf32)
    gemm_tf32_kernel<<<dim3(8, 4, 2), 256>>>(p_ao, out_w, out_b, x, p_x1, 512, 0, nullptr, nullptr);
    // batchnorm2 stats only (affine fused into mlp1 staging)
    bn_stats_kernel<<<512, 256>>>(p_x1, n2_g, n2_b, p_sc, p_sh);
    // mlp1 + gelu (tf32) with bn2 affine fused
    gemm_tf32_kernel<<<dim3(8, 16, 2), 256>>>(p_x1, mlp_w1, mlp_b1, nullptr, p_m1, 512, 1, p_sc, p_sh);
    // mlp2 + residual (tf32)
    gemm_tf32_kernel<<<dim3(8, 4, 2), 256>>>(p_m1, mlp_w2, mlp_b2, p_x1, out, 2048, 0, nullptr, nullptr);
}